// round 2
// baseline (speedup 1.0000x reference)
#include <cuda_runtime.h>

// ---------------------------------------------------------------------------
// EfficientViT block, fp32. Token-major (NHWC) internal layout.
// B=64, C=256, H=W=28 -> TOK = 50176 tokens. NH=4 heads, KD=16, D=64, win 7x7.
// ---------------------------------------------------------------------------

#define TOK   50176
#define CDIM  256
#define HIDD  512
#define QKVC  384
#define NHD   4
#define KDIM  16
#define DV    64
#define NB    64
#define HW2   28

// scratch (global allocs are forbidden; __device__ arrays are the sanctioned path)
__device__ float g_xA[TOK * CDIM];     // current activation, NHWC
__device__ float g_xB[TOK * CDIM];     // second activation buffer
__device__ float g_h [TOK * HIDD];     // ffn hidden
__device__ float g_qkv[TOK * QKVC];   // qkv (post-bn)
__device__ float g_q2[TOK * NHD * KDIM]; // q after 5x5 dws conv
__device__ float g_ob[TOK * CDIM];    // attention output (relu'd)
__device__ float g_wt[688128];        // transposed weights [K,N]

// weight offsets inside g_wt
#define WT_F0W1 0
#define WT_F0W2 131072
#define WT_QKV  262144
#define WT_PROJ 360448
#define WT_F1W1 425984
#define WT_F1W2 557056

// ---------------------------------------------------------------------------
// f32x2 packed-FMA helpers (Blackwell FFMA2 — 2x fp32 FMA throughput)
// ---------------------------------------------------------------------------
__device__ __forceinline__ unsigned long long pack2(float lo, float hi) {
    unsigned long long r;
    asm("mov.b64 %0, {%1,%2};" : "=l"(r) : "f"(lo), "f"(hi));
    return r;
}
__device__ __forceinline__ void ffma2(unsigned long long& d,
                                      unsigned long long a,
                                      unsigned long long b) {
    asm("fma.rn.f32x2 %0, %1, %2, %3;" : "=l"(d) : "l"(a), "l"(b), "l"(d));
}
__device__ __forceinline__ float2 unpack2(unsigned long long v) {
    float2 f;
    asm("mov.b64 {%0,%1}, %2;" : "=f"(f.x), "=f"(f.y) : "l"(v));
    return f;
}

// ---------------------------------------------------------------------------
// Weight transpose: src [N,K] (OIHW 1x1) -> dst [K,N]
// ---------------------------------------------------------------------------
__global__ void wtrans_kernel(const float* __restrict__ src,
                              float* __restrict__ dst, int N, int K) {
    int i = blockIdx.x * 256 + threadIdx.x;
    if (i < N * K) {
        int n = i / K, k = i % K;
        dst[k * N + n] = src[i];
    }
}

// ---------------------------------------------------------------------------
// SGEMM: C[M,N] = epi( A[M,K] @ Bt[K,N] )   (Bt pre-transposed weights)
// epi 0: v = acc*s[n]+b[n]
// epi 1: v = relu(acc*s[n]+b[n])
// epi 2: v = resid[m,n] + acc*s[n]+b[n]
// 128x128x16 tile, 256 threads, 8x8 per thread, FFMA2 inner product.
// Requires M%128==0, N%128==0, K%16==0 (true for all calls here).
// ---------------------------------------------------------------------------
__global__ void __launch_bounds__(256, 2) gemm_kernel(
    const float* __restrict__ A, const float* __restrict__ Bt,
    const float* __restrict__ sc, const float* __restrict__ bi,
    const float* __restrict__ resid, float* __restrict__ C,
    int M, int N, int K, int epi)
{
    __shared__ __align__(16) float As[16][132];  // [k][m], padded
    __shared__ __align__(16) float Bs[16][128];  // [k][n]

    int tid = threadIdx.x;
    int tx = tid & 15, ty = tid >> 4;
    int bm = blockIdx.y << 7, bn = blockIdx.x << 7;

    unsigned long long acc2[8][4];
    const unsigned long long z2 = pack2(0.f, 0.f);
#pragma unroll
    for (int i = 0; i < 8; i++)
#pragma unroll
        for (int j = 0; j < 4; j++) acc2[i][j] = z2;

    for (int kt = 0; kt < K; kt += 16) {
        // A tile: 128 rows x 16 k (k-inner reads, coalesced 64B per row)
#pragma unroll
        for (int p = 0; p < 8; p++) {
            int idx = (p << 8) + tid;
            int m = idx >> 4, k = idx & 15;
            As[k][m] = A[(long)(bm + m) * K + kt + k];
        }
        // B tile: 16 k x 128 n (n-inner, fully coalesced)
#pragma unroll
        for (int p = 0; p < 8; p++) {
            int idx = (p << 8) + tid;
            int k = idx >> 7, n = idx & 127;
            Bs[k][n] = Bt[(long)(kt + k) * N + bn + n];
        }
        __syncthreads();

#pragma unroll
        for (int k = 0; k < 16; k++) {
            float4 a0 = *(const float4*)&As[k][ty * 8];
            float4 a1 = *(const float4*)&As[k][ty * 8 + 4];
            float4 b0 = *(const float4*)&Bs[k][tx * 8];
            float4 b1 = *(const float4*)&Bs[k][tx * 8 + 4];
            float av[8] = {a0.x, a0.y, a0.z, a0.w, a1.x, a1.y, a1.z, a1.w};
            unsigned long long bp[4];
            bp[0] = pack2(b0.x, b0.y);
            bp[1] = pack2(b0.z, b0.w);
            bp[2] = pack2(b1.x, b1.y);
            bp[3] = pack2(b1.z, b1.w);
#pragma unroll
            for (int i = 0; i < 8; i++) {
                unsigned long long ad = pack2(av[i], av[i]);
#pragma unroll
                for (int j = 0; j < 4; j++) ffma2(acc2[i][j], ad, bp[j]);
            }
        }
        __syncthreads();
    }

    // epilogue
    float svec[8], bvec[8];
#pragma unroll
    for (int j = 0; j < 8; j++) {
        int n = bn + tx * 8 + j;
        svec[j] = sc[n];
        bvec[j] = bi[n];
    }
#pragma unroll
    for (int i = 0; i < 8; i++) {
        long row = bm + ty * 8 + i;
        float* Crow = C + row * N + bn + tx * 8;
        const float* Rrow = (epi == 2) ? (resid + row * N + bn + tx * 8) : nullptr;
        float out[8];
#pragma unroll
        for (int j = 0; j < 4; j++) {
            float2 v = unpack2(acc2[i][j]);
            out[2 * j] = v.x;
            out[2 * j + 1] = v.y;
        }
#pragma unroll
        for (int j = 0; j < 8; j++) {
            float v = out[j] * svec[j] + bvec[j];
            if (epi == 1) v = fmaxf(v, 0.f);
            else if (epi == 2) v += Rrow[j];
            Crow[j] = v;
        }
    }
}

// ---------------------------------------------------------------------------
// dw0: NCHW input -> NHWC g_xA,  xA = x + bn(dw3x3(x))
// block: (ctile of 64, h, b); 256 threads
// ---------------------------------------------------------------------------
__global__ void __launch_bounds__(256) dw0_kernel(
    const float* __restrict__ x, const float* __restrict__ w,
    const float* __restrict__ s, const float* __restrict__ bb)
{
    __shared__ float sx[3][64][29];   // padded: 28+1 to kill bank conflicts
    __shared__ float wsm[64][9];
    __shared__ float ssm[64], bsm[64];
    int c0 = blockIdx.x * 64;
    int h = blockIdx.y;
    int b = blockIdx.z;
    int tid = threadIdx.x;

    for (int i = tid; i < 64 * 9; i += 256) {
        int c = i / 9, k = i % 9;
        wsm[c][k] = w[(c0 + c) * 9 + k];
    }
    if (tid < 64) { ssm[tid] = s[c0 + tid]; bsm[tid] = bb[c0 + tid]; }

    for (int i = tid; i < 3 * 64 * 28; i += 256) {
        int row = i / 1792;
        int rem = i % 1792;
        int c = rem / 28, ww = rem % 28;
        int hh = h - 1 + row;
        float v = 0.f;
        if (hh >= 0 && hh < 28)
            v = x[(((long)(b * 256 + c0 + c)) * 28 + hh) * 28 + ww];
        sx[row][c][ww] = v;
    }
    __syncthreads();

    for (int i = tid; i < 64 * 28; i += 256) {
        int cl = i & 63, ww = i >> 6;
        float acc = 0.f;
#pragma unroll
        for (int dy = 0; dy < 3; dy++)
#pragma unroll
            for (int dx = 0; dx < 3; dx++) {
                int w2 = ww + dx - 1;
                if (w2 >= 0 && w2 < 28)
                    acc += wsm[cl][dy * 3 + dx] * sx[dy][cl][w2];
            }
        long t = (long)(b * 28 + h) * 28 + ww;
        g_xA[t * 256 + c0 + cl] = sx[1][cl][ww] + ssm[cl] * acc + bsm[cl];
    }
}

// ---------------------------------------------------------------------------
// dw1: NHWC -> NHWC, xB = xA + bn(dw3x3(xA)). block = 1 token, 256 thr = C
// ---------------------------------------------------------------------------
__global__ void __launch_bounds__(256) dw1_kernel(
    const float* __restrict__ w, const float* __restrict__ s,
    const float* __restrict__ bb)
{
    int t = blockIdx.x;
    int c = threadIdx.x;
    int b = t / 784, rem = t % 784, h = rem / 28, ww = rem % 28;
    float wr[9];
#pragma unroll
    for (int k = 0; k < 9; k++) wr[k] = w[c * 9 + k];
    float acc = 0.f;
#pragma unroll
    for (int dy = 0; dy < 3; dy++) {
        int h2 = h + dy - 1;
        if (h2 < 0 || h2 >= 28) continue;
#pragma unroll
        for (int dx = 0; dx < 3; dx++) {
            int w2 = ww + dx - 1;
            if (w2 < 0 || w2 >= 28) continue;
            acc += wr[dy * 3 + dx] * g_xA[((long)(b * 784 + h2 * 28 + w2)) * 256 + c];
        }
    }
    float center = g_xA[(long)t * 256 + c];
    g_xB[(long)t * 256 + c] = center + s[c] * acc + bb[c];
}

// ---------------------------------------------------------------------------
// dws: 5x5 depthwise conv on q channels of g_qkv -> g_q2 (per head, per kc)
// 256 threads = 4 tokens x 64 (head,kc) channels
// ---------------------------------------------------------------------------
__global__ void __launch_bounds__(256) dws_kernel(
    const float* __restrict__ w, const float* __restrict__ s,
    const float* __restrict__ bb)
{
    int t = blockIdx.x * 4 + (threadIdx.x >> 6);
    int ch = threadIdx.x & 63;
    int head = ch >> 4, kc = ch & 15;
    int qc = head * 96 + kc;
    int b = t / 784, rem = t % 784, h = rem / 28, ww = rem % 28;
    float acc = 0.f;
#pragma unroll
    for (int dy = 0; dy < 5; dy++) {
        int h2 = h + dy - 2;
        if (h2 < 0 || h2 >= 28) continue;
#pragma unroll
        for (int dx = 0; dx < 5; dx++) {
            int w2 = ww + dx - 2;
            if (w2 < 0 || w2 >= 28) continue;
            acc += w[ch * 25 + dy * 5 + dx] *
                   g_qkv[((long)(b * 784 + h2 * 28 + w2)) * 384 + qc];
        }
    }
    g_q2[(long)t * 64 + ch] = s[ch] * acc + bb[ch];
}

// ---------------------------------------------------------------------------
// per-window attention (7x7 = 49 tokens). One block per (window, head, batch).
// reads g_q2 (q, post-dws), g_qkv (k,v), writes relu(o) into g_ob.
// ---------------------------------------------------------------------------
__global__ void __launch_bounds__(128) attn_kernel(const float* __restrict__ pos)
{
    int wi = blockIdx.x >> 2, wj = blockIdx.x & 3;
    int head = blockIdx.y, b = blockIdx.z;
    int tid = threadIdx.x;

    __shared__ float sq[49 * 17];
    __shared__ float sk[49 * 17];
    __shared__ __align__(16) float sv[49 * 64];
    __shared__ float ss[49 * 50];
    __shared__ int stok[49];

    if (tid < 49) {
        int r = tid;
        stok[r] = b * 784 + (wi * 7 + r / 7) * 28 + wj * 7 + (r % 7);
    }
    __syncthreads();

    for (int i = tid; i < 49 * 16; i += 128) {
        int r = i >> 4, c = i & 15;
        long t = stok[r];
        sq[r * 17 + c] = g_q2[t * 64 + head * 16 + c];
        sk[r * 17 + c] = g_qkv[t * 384 + head * 96 + 16 + c];
    }
    for (int i = tid; i < 49 * 64; i += 128) {
        int r = i >> 6, c = i & 63;
        sv[i] = g_qkv[(long)stok[r] * 384 + head * 96 + 32 + c];
    }
    __syncthreads();

    const float* pe = pos + head * 49 * 49;
    for (int i = tid; i < 49 * 49; i += 128) {
        int qr = i / 49, kr = i % 49;
        float d = 0.f;
#pragma unroll
        for (int c = 0; c < 16; c++)
            d += sq[qr * 17 + c] * sk[kr * 17 + c];
        ss[qr * 50 + kr] = d * 0.25f + pe[i];
    }
    __syncthreads();

    if (tid < 49) {
        float* row = ss + tid * 50;
        float mx = -1e30f;
        for (int k = 0; k < 49; k++) mx = fmaxf(mx, row[k]);
        float sum = 0.f;
        for (int k = 0; k < 49; k++) {
            float e = __expf(row[k] - mx);
            row[k] = e;
            sum += e;
        }
        float inv = 1.f / sum;
        for (int k = 0; k < 49; k++) row[k] *= inv;
    }
    __syncthreads();

    for (int i = tid; i < 49 * 16; i += 128) {
        int qr = i >> 4, d0 = (i & 15) << 2;
        float4 acc = make_float4(0.f, 0.f, 0.f, 0.f);
        for (int k = 0; k < 49; k++) {
            float p = ss[qr * 50 + k];
            float4 v = *(const float4*)&sv[k * 64 + d0];
            acc.x = fmaf(p, v.x, acc.x);
            acc.y = fmaf(p, v.y, acc.y);
            acc.z = fmaf(p, v.z, acc.z);
            acc.w = fmaf(p, v.w, acc.w);
        }
        long t = stok[qr];
        float* o = &g_ob[t * 256 + head * 64 + d0];
        o[0] = fmaxf(acc.x, 0.f);
        o[1] = fmaxf(acc.y, 0.f);
        o[2] = fmaxf(acc.z, 0.f);
        o[3] = fmaxf(acc.w, 0.f);
    }
}

// ---------------------------------------------------------------------------
// final transpose: NHWC g_xA -> NCHW d_out  (per image [784,256] -> [256,784])
// ---------------------------------------------------------------------------
__global__ void trans_out_kernel(float* __restrict__ out)
{
    __shared__ float tile[32][33];
    int t0 = blockIdx.x * 32, c0 = blockIdx.y * 32, b = blockIdx.z;
    int tx = threadIdx.x, ty = threadIdx.y;
#pragma unroll
    for (int r = 0; r < 4; r++) {
        int t = t0 + ty + r * 8;
        if (t < 784)
            tile[ty + r * 8][tx] = g_xA[((long)(b * 784 + t)) * 256 + c0 + tx];
    }
    __syncthreads();
#pragma unroll
    for (int r = 0; r < 4; r++) {
        int c = c0 + ty + r * 8;
        int t = t0 + tx;
        if (t < 784)
            out[((long)(b * 256 + c)) * 784 + t] = tile[tx][ty + r * 8];
    }
}

// ---------------------------------------------------------------------------
extern "C" void kernel_launch(void* const* d_in, const int* in_sizes, int n_in,
                              void* d_out, int out_size)
{
    const float* in[32];
    for (int i = 0; i < n_in && i < 32; i++) in[i] = (const float*)d_in[i];

    // detect ordering: signature order has ffn0_w1 (131072) at idx 4,
    // setup-dict order has dw1_w (2304) there.
    int idw0, idw1, iffn0, iffn1, iqkv, idws, iproj, ipos;
    if (in_sizes[4] > 100000) { // reference-signature order
        idw0 = 1;  iffn0 = 4;  iqkv = 10; idws = 13; iproj = 16;
        ipos = 19; idw1 = 20;  iffn1 = 23;
    } else {                    // setup_inputs dict order
        idw0 = 1;  idw1 = 4;   iffn0 = 7;  iffn1 = 13;
        iqkv = 19; idws = 22;  iproj = 25; ipos = 28;
    }

    const float* x     = in[0];
    const float* dw0_w = in[idw0],  * dw0_s = in[idw0 + 1], * dw0_b = in[idw0 + 2];
    const float* dw1_w = in[idw1],  * dw1_s = in[idw1 + 1], * dw1_b = in[idw1 + 2];
    const float* f0w1 = in[iffn0],     * f0s1 = in[iffn0 + 1], * f0b1 = in[iffn0 + 2];
    const float* f0w2 = in[iffn0 + 3], * f0s2 = in[iffn0 + 4], * f0b2 = in[iffn0 + 5];
    const float* f1w1 = in[iffn1],     * f1s1 = in[iffn1 + 1], * f1b1 = in[iffn1 + 2];
    const float* f1w2 = in[iffn1 + 3], * f1s2 = in[iffn1 + 4], * f1b2 = in[iffn1 + 5];
    const float* qkv_w = in[iqkv],  * qkv_s = in[iqkv + 1],  * qkv_b = in[iqkv + 2];
    const float* dws_w = in[idws],  * dws_s = in[idws + 1],  * dws_b = in[idws + 2];
    const float* proj_w = in[iproj], * proj_s = in[iproj + 1], * proj_b = in[iproj + 2];
    const float* pos = in[ipos];

    float *pxA, *pxB, *ph, *pqkv, *pob, *pwt;
    cudaGetSymbolAddress((void**)&pxA, g_xA);
    cudaGetSymbolAddress((void**)&pxB, g_xB);
    cudaGetSymbolAddress((void**)&ph,  g_h);
    cudaGetSymbolAddress((void**)&pqkv, g_qkv);
    cudaGetSymbolAddress((void**)&pob, g_ob);
    cudaGetSymbolAddress((void**)&pwt, g_wt);

    // transpose weights once per call (tiny)
    wtrans_kernel<<<(131072 + 255) / 256, 256>>>(f0w1, pwt + WT_F0W1, 512, 256);
    wtrans_kernel<<<(131072 + 255) / 256, 256>>>(f0w2, pwt + WT_F0W2, 256, 512);
    wtrans_kernel<<<( 98304 + 255) / 256, 256>>>(qkv_w, pwt + WT_QKV, 384, 256);
    wtrans_kernel<<<( 65536 + 255) / 256, 256>>>(proj_w, pwt + WT_PROJ, 256, 256);
    wtrans_kernel<<<(131072 + 255) / 256, 256>>>(f1w1, pwt + WT_F1W1, 512, 256);
    wtrans_kernel<<<(131072 + 255) / 256, 256>>>(f1w2, pwt + WT_F1W2, 256, 512);

    // 1. xA = x + bn(dw3x3(x))    (NCHW -> NHWC)
    dw0_kernel<<<dim3(4, 28, 64), 256>>>(x, dw0_w, dw0_s, dw0_b);

    // 2. ffn0
    gemm_kernel<<<dim3(4, 392), 256>>>(pxA, pwt + WT_F0W1, f0s1, f0b1, nullptr,
                                       ph, TOK, 512, 256, 1);
    gemm_kernel<<<dim3(2, 392), 256>>>(ph, pwt + WT_F0W2, f0s2, f0b2, pxA,
                                       pxA, TOK, 256, 512, 2);

    // 3. attention block
    gemm_kernel<<<dim3(3, 392), 256>>>(pxA, pwt + WT_QKV, qkv_s, qkv_b, nullptr,
                                       pqkv, TOK, 384, 256, 0);
    dws_kernel<<<TOK / 4, 256>>>(dws_w, dws_s, dws_b);
    attn_kernel<<<dim3(16, 4, 64), 128>>>(pos);
    gemm_kernel<<<dim3(2, 392), 256>>>(pob, pwt + WT_PROJ, proj_s, proj_b, pxA,
                                       pxA, TOK, 256, 256, 2);

    // 4. xB = xA + bn(dw3x3(xA))
    dw1_kernel<<<TOK, 256>>>(dw1_w, dw1_s, dw1_b);

    // 5. ffn1 (result into xA)
    gemm_kernel<<<dim3(4, 392), 256>>>(pxB, pwt + WT_F1W1, f1s1, f1b1, nullptr,
                                       ph, TOK, 512, 256, 1);
    gemm_kernel<<<dim3(2, 392), 256>>>(ph, pwt + WT_F1W2, f1s2, f1b2, pxB,
                                       pxA, TOK, 256, 512, 2);

    // 6. NHWC -> NCHW output
    trans_out_kernel<<<dim3(25, 8, 64), dim3(32, 8)>>>((float*)d_out);
}

// round 8
// speedup vs baseline: 1.7555x; 1.7555x over previous
#include <cuda_runtime.h>
#include <cuda_bf16.h>
#include <cstdint>

// ---------------------------------------------------------------------------
// EfficientViT block. GEMMs via mma.sync bf16 (HMMA) with bf16x2 hi/lo split.
// Token-major internal layout. B=64, C=256, 28x28 -> TOK=50176. Win 7x7.
// NOTE: harness compiles via compute_103 PTX (no 'a') -> tcgen05 unavailable;
// mma.sync/ldmatrix are baseline sm_80+ features and DO compile.
// ---------------------------------------------------------------------------

#define TOK   50176

// scratch
__device__ float g_xA[TOK * 256];
__device__ float g_xB[TOK * 256];
__device__ float g_h [TOK * 512];
__device__ float g_qkv[TOK * 384];
__device__ float g_q2[TOK * 64];
__device__ float g_ob[TOK * 256];
__device__ __align__(16) unsigned char g_wtB[2752512]; // bf16 hi/lo weight images

// weight-image offsets (bytes). Layout per weight: hi[N*K] bf16, then lo[N*K].
#define WB_F0W1 0
#define WB_F0W2 524288
#define WB_QKV  1048576
#define WB_PROJ 1441792
#define WB_F1W1 1703936
#define WB_F1W2 2228224

__device__ __forceinline__ uint32_t smem_u32(const void* p) {
    uint32_t a;
    asm("{ .reg .u64 t; cvta.to.shared.u64 t, %1; cvt.u32.u64 %0, t; }"
        : "=r"(a) : "l"(p));
    return a;
}

__device__ __forceinline__ void ldsm4(uint32_t* r, uint32_t addr) {
    asm volatile("ldmatrix.sync.aligned.m8n8.x4.shared.b16 {%0,%1,%2,%3}, [%4];"
        : "=r"(r[0]), "=r"(r[1]), "=r"(r[2]), "=r"(r[3]) : "r"(addr));
}

__device__ __forceinline__ void mma16816(float* c, const uint32_t* a,
                                         const uint32_t* b) {
    asm volatile(
        "mma.sync.aligned.m16n8k16.row.col.f32.bf16.bf16.f32 "
        "{%0,%1,%2,%3}, {%4,%5,%6,%7}, {%8,%9}, {%0,%1,%2,%3};"
        : "+f"(c[0]), "+f"(c[1]), "+f"(c[2]), "+f"(c[3])
        : "r"(a[0]), "r"(a[1]), "r"(a[2]), "r"(a[3]), "r"(b[0]), "r"(b[1]));
}

// smem tile stride: 40 bf16 (80 B) -> 8 consecutive rows hit distinct 128B
// phases (0,80,32,112,64,16,96,48): ldmatrix conflict-free.
#define TS 40

// A-frag ldmatrix.x4 address: regs = (m0-7,k0-7),(m8-15,k0-7),(m0-7,k8-15),(m8-15,k8-15)
__device__ __forceinline__ uint32_t a_addr(uint32_t base, int m, int k, int lane) {
    int g = lane >> 3, r = lane & 7;
    int row = m + ((g & 1) << 3) + r;
    int col = k + ((g >> 1) << 3);
    return base + (row * TS + col) * 2;
}
// B-frag ldmatrix.x4 address: regs = (n0-7,k0-7),(n0-7,k8-15),(n8-15,k0-7),(n8-15,k8-15)
__device__ __forceinline__ uint32_t b_addr(uint32_t base, int n, int k, int lane) {
    int g = lane >> 3, r = lane & 7;
    int row = n + ((g >> 1) << 3) + r;
    int col = k + ((g & 1) << 3);
    return base + (row * TS + col) * 2;
}

// ---------------------------------------------------------------------------
// Weight split: w [N,K] fp32 -> hi bf16 [N*K] then lo bf16 [N*K] (row-major)
// ---------------------------------------------------------------------------
__global__ void wconv_kernel(const float* __restrict__ w,
                             unsigned char* __restrict__ dst, int N, int K) {
    int i = blockIdx.x * 256 + threadIdx.x;
    if (i >= N * K) return;
    float x = w[i];
    __nv_bfloat16 h = __float2bfloat16(x);
    __nv_bfloat16 l = __float2bfloat16(x - __bfloat162float(h));
    ((__nv_bfloat16*)dst)[i] = h;
    ((__nv_bfloat16*)dst)[(long)N * K + i] = l;
}

// ---------------------------------------------------------------------------
// HMMA GEMM: C[M,N] = epi( A[M,K] @ W[N,K]^T ), bf16 hi/lo split, fp32 accum.
// grid = (N/128, M/128), 256 threads (8 warps, 2m x 4n), warp tile 64x32.
// epi: 0 = s*acc+b ; 1 = relu(s*acc+b) ; 2 = resid + s*acc+b
// ---------------------------------------------------------------------------
__global__ void __launch_bounds__(256, 2) mm_gemm(
    const float* __restrict__ A, const unsigned char* __restrict__ Bimg,
    const float* __restrict__ sc, const float* __restrict__ bi,
    const float* __restrict__ resid, float* __restrict__ C,
    int N, int K, int epi)
{
    __shared__ __align__(16) uint16_t sA[2][128 * TS];  // hi, lo
    __shared__ __align__(16) uint16_t sB[2][128 * TS];  // hi, lo

    int tid = threadIdx.x, lane = tid & 31, wid = tid >> 5;
    int wm = (wid & 1) << 6;           // warp m offset (0/64)
    int wn = (wid >> 1) << 5;          // warp n offset (0/32/64/96)
    long bm = (long)blockIdx.y << 7;
    int bn = blockIdx.x << 7;
    long loOff = (long)N * K;          // elements between hi and lo images

    float acc[4][4][4] = {};

    uint32_t sAh = smem_u32(sA[0]), sAl = smem_u32(sA[1]);
    uint32_t sBh = smem_u32(sB[0]), sBl = smem_u32(sB[1]);

    int rowL = tid >> 1, k0L = (tid & 1) << 4;   // loader assignment

    for (int kt = 0; kt < K; kt += 32) {
        // --- load + split A tile [128][32] fp32 -> hi/lo bf16 smem ---
        {
            const float* s = A + (bm + rowL) * K + kt + k0L;
            float4 v0 = *(const float4*)s;
            float4 v1 = *(const float4*)(s + 4);
            float4 v2 = *(const float4*)(s + 8);
            float4 v3 = *(const float4*)(s + 12);
            float f[16] = {v0.x, v0.y, v0.z, v0.w, v1.x, v1.y, v1.z, v1.w,
                           v2.x, v2.y, v2.z, v2.w, v3.x, v3.y, v3.z, v3.w};
            uint32_t hw[8], lw[8];
#pragma unroll
            for (int j = 0; j < 8; j++) {
                __nv_bfloat16 h0 = __float2bfloat16(f[2 * j]);
                __nv_bfloat16 h1 = __float2bfloat16(f[2 * j + 1]);
                __nv_bfloat16 l0 = __float2bfloat16(f[2 * j] - __bfloat162float(h0));
                __nv_bfloat16 l1 = __float2bfloat16(f[2 * j + 1] - __bfloat162float(h1));
                hw[j] = (uint32_t)__bfloat16_as_ushort(h0) |
                        ((uint32_t)__bfloat16_as_ushort(h1) << 16);
                lw[j] = (uint32_t)__bfloat16_as_ushort(l0) |
                        ((uint32_t)__bfloat16_as_ushort(l1) << 16);
            }
            uint16_t* ph = &sA[0][rowL * TS + k0L];
            uint16_t* pl = &sA[1][rowL * TS + k0L];
            *(uint4*)ph       = make_uint4(hw[0], hw[1], hw[2], hw[3]);
            *(uint4*)(ph + 8) = make_uint4(hw[4], hw[5], hw[6], hw[7]);
            *(uint4*)pl       = make_uint4(lw[0], lw[1], lw[2], lw[3]);
            *(uint4*)(pl + 8) = make_uint4(lw[4], lw[5], lw[6], lw[7]);
        }
        // --- load B tile [128n][32k] hi/lo from pre-split images ---
        {
            long e = (long)(bn + rowL) * K + kt + k0L;
            const uint4* srch = (const uint4*)(Bimg + e * 2);
            const uint4* srcl = (const uint4*)(Bimg + (loOff + e) * 2);
            uint16_t* ph = &sB[0][rowL * TS + k0L];
            uint16_t* pl = &sB[1][rowL * TS + k0L];
            *(uint4*)ph       = srch[0];
            *(uint4*)(ph + 8) = srch[1];
            *(uint4*)pl       = srcl[0];
            *(uint4*)(pl + 8) = srcl[1];
        }
        __syncthreads();

#pragma unroll
        for (int kk = 0; kk < 32; kk += 16) {
            uint32_t ah[4][4], al[4][4], bh[2][4], bl[2][4];
#pragma unroll
            for (int mt = 0; mt < 4; mt++)
                ldsm4(ah[mt], a_addr(sAh, wm + mt * 16, kk, lane));
#pragma unroll
            for (int h = 0; h < 2; h++)
                ldsm4(bh[h], b_addr(sBh, wn + h * 16, kk, lane));
#pragma unroll
            for (int mt = 0; mt < 4; mt++)
#pragma unroll
                for (int nt = 0; nt < 4; nt++)
                    mma16816(acc[mt][nt], ah[mt], &bh[nt >> 1][(nt & 1) * 2]);
#pragma unroll
            for (int h = 0; h < 2; h++)
                ldsm4(bl[h], b_addr(sBl, wn + h * 16, kk, lane));
#pragma unroll
            for (int mt = 0; mt < 4; mt++)
#pragma unroll
                for (int nt = 0; nt < 4; nt++)
                    mma16816(acc[mt][nt], ah[mt], &bl[nt >> 1][(nt & 1) * 2]);
#pragma unroll
            for (int mt = 0; mt < 4; mt++)
                ldsm4(al[mt], a_addr(sAl, wm + mt * 16, kk, lane));
#pragma unroll
            for (int mt = 0; mt < 4; mt++)
#pragma unroll
                for (int nt = 0; nt < 4; nt++)
                    mma16816(acc[mt][nt], al[mt], &bh[nt >> 1][(nt & 1) * 2]);
        }
        __syncthreads();
    }

    // epilogue: lane q=l>>2 holds rows q,q+8; cols 2*(l&3)+{0,1} per 16x8 frag
    int q = lane >> 2, tq = lane & 3;
#pragma unroll
    for (int nt = 0; nt < 4; nt++) {
        int n = bn + wn + nt * 8 + tq * 2;
        float2 s2 = *(const float2*)(sc + n);
        float2 b2 = *(const float2*)(bi + n);
#pragma unroll
        for (int mt = 0; mt < 4; mt++) {
#pragma unroll
            for (int half = 0; half < 2; half++) {
                long m = bm + wm + mt * 16 + q + half * 8;
                float v0 = acc[mt][nt][half * 2 + 0] * s2.x + b2.x;
                float v1 = acc[mt][nt][half * 2 + 1] * s2.y + b2.y;
                if (epi == 1) {
                    v0 = fmaxf(v0, 0.f);
                    v1 = fmaxf(v1, 0.f);
                } else if (epi == 2) {
                    float2 r2 = *(const float2*)(resid + m * N + n);
                    v0 += r2.x;
                    v1 += r2.y;
                }
                float2 o;
                o.x = v0; o.y = v1;
                *(float2*)(C + m * N + n) = o;
            }
        }
    }
}

// ---------------------------------------------------------------------------
// dw0: NCHW input -> NHWC g_xA,  xA = x + bn(dw3x3(x))
// ---------------------------------------------------------------------------
__global__ void __launch_bounds__(256) dw0_kernel(
    const float* __restrict__ x, const float* __restrict__ w,
    const float* __restrict__ s, const float* __restrict__ bb)
{
    __shared__ float sx[3][64][29];
    __shared__ float wsm[64][9];
    __shared__ float ssm[64], bsm[64];
    int c0 = blockIdx.x * 64;
    int h = blockIdx.y;
    int b = blockIdx.z;
    int tid = threadIdx.x;

    for (int i = tid; i < 64 * 9; i += 256) {
        int c = i / 9, k = i % 9;
        wsm[c][k] = w[(c0 + c) * 9 + k];
    }
    if (tid < 64) { ssm[tid] = s[c0 + tid]; bsm[tid] = bb[c0 + tid]; }

    for (int i = tid; i < 3 * 64 * 28; i += 256) {
        int row = i / 1792;
        int rem = i % 1792;
        int c = rem / 28, ww = rem % 28;
        int hh = h - 1 + row;
        float v = 0.f;
        if (hh >= 0 && hh < 28)
            v = x[(((long)(b * 256 + c0 + c)) * 28 + hh) * 28 + ww];
        sx[row][c][ww] = v;
    }
    __syncthreads();

    for (int i = tid; i < 64 * 28; i += 256) {
        int cl = i & 63, ww = i >> 6;
        float acc = 0.f;
#pragma unroll
        for (int dy = 0; dy < 3; dy++)
#pragma unroll
            for (int dx = 0; dx < 3; dx++) {
                int w2 = ww + dx - 1;
                if (w2 >= 0 && w2 < 28)
                    acc += wsm[cl][dy * 3 + dx] * sx[dy][cl][w2];
            }
        long t = (long)(b * 28 + h) * 28 + ww;
        g_xA[t * 256 + c0 + cl] = sx[1][cl][ww] + ssm[cl] * acc + bsm[cl];
    }
}

// ---------------------------------------------------------------------------
// dw1: NHWC -> NHWC, xB = xA + bn(dw3x3(xA))
// ---------------------------------------------------------------------------
__global__ void __launch_bounds__(256) dw1_kernel(
    const float* __restrict__ w, const float* __restrict__ s,
    const float* __restrict__ bb)
{
    int t = blockIdx.x;
    int c = threadIdx.x;
    int b = t / 784, rem = t % 784, h = rem / 28, ww = rem % 28;
    float wr[9];
#pragma unroll
    for (int k = 0; k < 9; k++) wr[k] = w[c * 9 + k];
    float acc = 0.f;
#pragma unroll
    for (int dy = 0; dy < 3; dy++) {
        int h2 = h + dy - 1;
        if (h2 < 0 || h2 >= 28) continue;
#pragma unroll
        for (int dx = 0; dx < 3; dx++) {
            int w2 = ww + dx - 1;
            if (w2 < 0 || w2 >= 28) continue;
            acc += wr[dy * 3 + dx] * g_xA[((long)(b * 784 + h2 * 28 + w2)) * 256 + c];
        }
    }
    float center = g_xA[(long)t * 256 + c];
    g_xB[(long)t * 256 + c] = center + s[c] * acc + bb[c];
}

// ---------------------------------------------------------------------------
// dws: 5x5 depthwise conv on q channels of g_qkv -> g_q2
// ---------------------------------------------------------------------------
__global__ void __launch_bounds__(256) dws_kernel(
    const float* __restrict__ w, const float* __restrict__ s,
    const float* __restrict__ bb)
{
    int t = blockIdx.x * 4 + (threadIdx.x >> 6);
    int ch = threadIdx.x & 63;
    int head = ch >> 4, kc = ch & 15;
    int qc = head * 96 + kc;
    int b = t / 784, rem = t % 784, h = rem / 28, ww = rem % 28;
    float acc = 0.f;
#pragma unroll
    for (int dy = 0; dy < 5; dy++) {
        int h2 = h + dy - 2;
        if (h2 < 0 || h2 >= 28) continue;
#pragma unroll
        for (int dx = 0; dx < 5; dx++) {
            int w2 = ww + dx - 2;
            if (w2 < 0 || w2 >= 28) continue;
            acc += w[ch * 25 + dy * 5 + dx] *
                   g_qkv[((long)(b * 784 + h2 * 28 + w2)) * 384 + qc];
        }
    }
    g_q2[(long)t * 64 + ch] = s[ch] * acc + bb[ch];
}

// ---------------------------------------------------------------------------
// per-window attention (7x7 = 49 tokens)
// ---------------------------------------------------------------------------
__global__ void __launch_bounds__(128) attn_kernel(const float* __restrict__ pos)
{
    int wi = blockIdx.x >> 2, wj = blockIdx.x & 3;
    int head = blockIdx.y, b = blockIdx.z;
    int tid = threadIdx.x;

    __shared__ float sq[49 * 17];
    __shared__ float sk[49 * 17];
    __shared__ __align__(16) float sv[49 * 64];
    __shared__ float ss[49 * 50];
    __shared__ int stok[49];

    if (tid < 49) {
        int r = tid;
        stok[r] = b * 784 + (wi * 7 + r / 7) * 28 + wj * 7 + (r % 7);
    }
    __syncthreads();

    for (int i = tid; i < 49 * 16; i += 128) {
        int r = i >> 4, c = i & 15;
        long t = stok[r];
        sq[r * 17 + c] = g_q2[t * 64 + head * 16 + c];
        sk[r * 17 + c] = g_qkv[t * 384 + head * 96 + 16 + c];
    }
    for (int i = tid; i < 49 * 64; i += 128) {
        int r = i >> 6, c = i & 63;
        sv[i] = g_qkv[(long)stok[r] * 384 + head * 96 + 32 + c];
    }
    __syncthreads();

    const float* pe = pos + head * 49 * 49;
    for (int i = tid; i < 49 * 49; i += 128) {
        int qr = i / 49, kr = i % 49;
        float d = 0.f;
#pragma unroll
        for (int c = 0; c < 16; c++)
            d += sq[qr * 17 + c] * sk[kr * 17 + c];
        ss[qr * 50 + kr] = d * 0.25f + pe[i];
    }
    __syncthreads();

    if (tid < 49) {
        float* row = ss + tid * 50;
        float mx = -1e30f;
        for (int k = 0; k < 49; k++) mx = fmaxf(mx, row[k]);
        float sum = 0.f;
        for (int k = 0; k < 49; k++) {
            float e = __expf(row[k] - mx);
            row[k] = e;
            sum += e;
        }
        float inv = 1.f / sum;
        for (int k = 0; k < 49; k++) row[k] *= inv;
    }
    __syncthreads();

    for (int i = tid; i < 49 * 16; i += 128) {
        int qr = i >> 4, d0 = (i & 15) << 2;
        float4 acc = make_float4(0.f, 0.f, 0.f, 0.f);
        for (int k = 0; k < 49; k++) {
            float p = ss[qr * 50 + k];
            float4 v = *(const float4*)&sv[k * 64 + d0];
            acc.x = fmaf(p, v.x, acc.x);
            acc.y = fmaf(p, v.y, acc.y);
            acc.z = fmaf(p, v.z, acc.z);
            acc.w = fmaf(p, v.w, acc.w);
        }
        long t = stok[qr];
        float* o = &g_ob[t * 256 + head * 64 + d0];
        o[0] = fmaxf(acc.x, 0.f);
        o[1] = fmaxf(acc.y, 0.f);
        o[2] = fmaxf(acc.z, 0.f);
        o[3] = fmaxf(acc.w, 0.f);
    }
}

// ---------------------------------------------------------------------------
// final transpose: NHWC g_xA -> NCHW d_out
// ---------------------------------------------------------------------------
__global__ void trans_out_kernel(float* __restrict__ out)
{
    __shared__ float tile[32][33];
    int t0 = blockIdx.x * 32, c0 = blockIdx.y * 32, b = blockIdx.z;
    int tx = threadIdx.x, ty = threadIdx.y;
#pragma unroll
    for (int r = 0; r < 4; r++) {
        int t = t0 + ty + r * 8;
        if (t < 784)
            tile[ty + r * 8][tx] = g_xA[((long)(b * 784 + t)) * 256 + c0 + tx];
    }
    __syncthreads();
#pragma unroll
    for (int r = 0; r < 4; r++) {
        int c = c0 + ty + r * 8;
        int t = t0 + tx;
        if (t < 784)
            out[((long)(b * 256 + c)) * 784 + t] = tile[tx][ty + r * 8];
    }
}

// ---------------------------------------------------------------------------
extern "C" void kernel_launch(void* const* d_in, const int* in_sizes, int n_in,
                              void* d_out, int out_size)
{
    const float* in[32];
    for (int i = 0; i < n_in && i < 32; i++) in[i] = (const float*)d_in[i];

    int idw0, idw1, iffn0, iffn1, iqkv, idws, iproj, ipos;
    if (in_sizes[4] > 100000) { // reference-signature order
        idw0 = 1;  iffn0 = 4;  iqkv = 10; idws = 13; iproj = 16;
        ipos = 19; idw1 = 20;  iffn1 = 23;
    } else {                    // setup_inputs dict order
        idw0 = 1;  idw1 = 4;   iffn0 = 7;  iffn1 = 13;
        iqkv = 19; idws = 22;  iproj = 25; ipos = 28;
    }

    const float* x     = in[0];
    const float* dw0_w = in[idw0],  * dw0_s = in[idw0 + 1], * dw0_b = in[idw0 + 2];
    const float* dw1_w = in[idw1],  * dw1_s = in[idw1 + 1], * dw1_b = in[idw1 + 2];
    const float* f0w1 = in[iffn0],     * f0s1 = in[iffn0 + 1], * f0b1 = in[iffn0 + 2];
    const float* f0w2 = in[iffn0 + 3], * f0s2 = in[iffn0 + 4], * f0b2 = in[iffn0 + 5];
    const float* f1w1 = in[iffn1],     * f1s1 = in[iffn1 + 1], * f1b1 = in[iffn1 + 2];
    const float* f1w2 = in[iffn1 + 3], * f1s2 = in[iffn1 + 4], * f1b2 = in[iffn1 + 5];
    const float* qkv_w = in[iqkv],  * qkv_s = in[iqkv + 1],  * qkv_b = in[iqkv + 2];
    const float* dws_w = in[idws],  * dws_s = in[idws + 1],  * dws_b = in[idws + 2];
    const float* proj_w = in[iproj], * proj_s = in[iproj + 1], * proj_b = in[iproj + 2];
    const float* pos = in[ipos];

    float *pxA, *pxB, *ph, *pqkv, *pob;
    unsigned char* pwtB;
    cudaGetSymbolAddress((void**)&pxA, g_xA);
    cudaGetSymbolAddress((void**)&pxB, g_xB);
    cudaGetSymbolAddress((void**)&ph,  g_h);
    cudaGetSymbolAddress((void**)&pqkv, g_qkv);
    cudaGetSymbolAddress((void**)&pob, g_ob);
    cudaGetSymbolAddress((void**)&pwtB, g_wtB);

    // split weights into bf16 hi/lo images (tiny)
    wconv_kernel<<<(512 * 256 + 255) / 256, 256>>>(f0w1, pwtB + WB_F0W1, 512, 256);
    wconv_kernel<<<(256 * 512 + 255) / 256, 256>>>(f0w2, pwtB + WB_F0W2, 256, 512);
    wconv_kernel<<<(384 * 256 + 255) / 256, 256>>>(qkv_w, pwtB + WB_QKV, 384, 256);
    wconv_kernel<<<(256 * 256 + 255) / 256, 256>>>(proj_w, pwtB + WB_PROJ, 256, 256);
    wconv_kernel<<<(512 * 256 + 255) / 256, 256>>>(f1w1, pwtB + WB_F1W1, 512, 256);
    wconv_kernel<<<(256 * 512 + 255) / 256, 256>>>(f1w2, pwtB + WB_F1W2, 256, 512);

    // 1. xA = x + bn(dw3x3(x))    (NCHW -> NHWC)
    dw0_kernel<<<dim3(4, 28, 64), 256>>>(x, dw0_w, dw0_s, dw0_b);

    // 2. ffn0
    mm_gemm<<<dim3(4, 392), 256>>>(pxA, pwtB + WB_F0W1, f0s1, f0b1, nullptr,
                                   ph, 512, 256, 1);
    mm_gemm<<<dim3(2, 392), 256>>>(ph, pwtB + WB_F0W2, f0s2, f0b2, pxA,
                                   pxA, 256, 512, 2);

    // 3. attention block
    mm_gemm<<<dim3(3, 392), 256>>>(pxA, pwtB + WB_QKV, qkv_s, qkv_b, nullptr,
                                   pqkv, 384, 256, 0);
    dws_kernel<<<TOK / 4, 256>>>(dws_w, dws_s, dws_b);
    attn_kernel<<<dim3(16, 4, 64), 128>>>(pos);
    mm_gemm<<<dim3(2, 392), 256>>>(pob, pwtB + WB_PROJ, proj_s, proj_b, pxA,
                                   pxA, 256, 256, 2);

    // 4. xB = xA + bn(dw3x3(xA))
    dw1_kernel<<<TOK, 256>>>(dw1_w, dw1_s, dw1_b);

    // 5. ffn1 (result into xA)
    mm_gemm<<<dim3(4, 392), 256>>>(pxB, pwtB + WB_F1W1, f1s1, f1b1, nullptr,
                                   ph, 512, 256, 1);
    mm_gemm<<<dim3(2, 392), 256>>>(ph, pwtB + WB_F1W2, f1s2, f1b2, pxB,
                                   pxA, 256, 512, 2);

    // 6. NHWC -> NCHW output
    trans_out_kernel<<<dim3(25, 8, 64), dim3(32, 8)>>>((float*)d_out);
}

// round 9
// speedup vs baseline: 2.0855x; 1.1880x over previous
#include <cuda_runtime.h>
#include <cuda_bf16.h>
#include <cstdint>

// ---------------------------------------------------------------------------
// EfficientViT block. GEMMs via mma.sync bf16 (HMMA) with bf16 hi/lo split.
// All GEMM operands pre-split to bf16 hi/lo images; cp.async double-buffered
// mainloop. Token-major internal layout. TOK=50176, C=256, win 7x7.
// ---------------------------------------------------------------------------

#define TOK   50176

// fp32 scratch
__device__ float g_xA[TOK * 256];
__device__ float g_xB[TOK * 256];
__device__ float g_qkv[TOK * 384];
__device__ float g_q2[TOK * 64];

// bf16 hi/lo activation images (hi at [0], lo at +TOK*C)
__device__ __align__(16) __nv_bfloat16 g_xAs[2 * TOK * 256];
__device__ __align__(16) __nv_bfloat16 g_hs [2 * TOK * 512];
__device__ __align__(16) __nv_bfloat16 g_obs[2 * TOK * 256];
__device__ __align__(16) __nv_bfloat16 g_xBs[2 * TOK * 256];

__device__ __align__(16) unsigned char g_wtB[2752512]; // bf16 hi/lo weight images
#define WB_F0W1 0
#define WB_F0W2 524288
#define WB_QKV  1048576
#define WB_PROJ 1441792
#define WB_F1W1 1703936
#define WB_F1W2 2228224

__device__ __forceinline__ uint32_t smem_u32(const void* p) {
    uint32_t a;
    asm("{ .reg .u64 t; cvta.to.shared.u64 t, %1; cvt.u32.u64 %0, t; }"
        : "=r"(a) : "l"(p));
    return a;
}
__device__ __forceinline__ void cpasync16(uint32_t saddr, const void* g) {
    asm volatile("cp.async.ca.shared.global [%0], [%1], 16;"
                 :: "r"(saddr), "l"(g));
}
__device__ __forceinline__ void ldsm4(uint32_t* r, uint32_t addr) {
    asm volatile("ldmatrix.sync.aligned.m8n8.x4.shared.b16 {%0,%1,%2,%3}, [%4];"
        : "=r"(r[0]), "=r"(r[1]), "=r"(r[2]), "=r"(r[3]) : "r"(addr));
}
__device__ __forceinline__ void mma16816(float* c, const uint32_t* a,
                                         const uint32_t* b) {
    asm volatile(
        "mma.sync.aligned.m16n8k16.row.col.f32.bf16.bf16.f32 "
        "{%0,%1,%2,%3}, {%4,%5,%6,%7}, {%8,%9}, {%0,%1,%2,%3};"
        : "+f"(c[0]), "+f"(c[1]), "+f"(c[2]), "+f"(c[3])
        : "r"(a[0]), "r"(a[1]), "r"(a[2]), "r"(a[3]), "r"(b[0]), "r"(b[1]));
}

// smem tile stride 40 bf16 (80B): 8 consecutive rows hit distinct 128B phases
#define TS 40

__device__ __forceinline__ uint32_t a_addr(uint32_t base, int m, int k, int lane) {
    int g = lane >> 3, r = lane & 7;
    return base + ((m + ((g & 1) << 3) + r) * TS + k + ((g >> 1) << 3)) * 2;
}
__device__ __forceinline__ uint32_t b_addr(uint32_t base, int n, int k, int lane) {
    int g = lane >> 3, r = lane & 7;
    return base + ((n + ((g >> 1) << 3) + r) * TS + k + ((g & 1) << 3)) * 2;
}

__device__ __forceinline__ void split_bf16(float v, __nv_bfloat16& h,
                                           __nv_bfloat16& l) {
    h = __float2bfloat16(v);
    l = __float2bfloat16(v - __bfloat162float(h));
}

// ---------------------------------------------------------------------------
// Weight split: w [N,K] fp32 -> hi bf16 [N*K] then lo bf16 [N*K] (row-major)
// ---------------------------------------------------------------------------
__global__ void wconv_kernel(const float* __restrict__ w,
                             unsigned char* __restrict__ dst, int N, int K) {
    int i = blockIdx.x * 256 + threadIdx.x;
    if (i >= N * K) return;
    __nv_bfloat16 h, l;
    split_bf16(w[i], h, l);
    ((__nv_bfloat16*)dst)[i] = h;
    ((__nv_bfloat16*)dst)[(long)N * K + i] = l;
}

// ---------------------------------------------------------------------------
// stage loader: A/B hi+lo tiles [128][32] bf16 each -> smem stage via cp.async
// stage layout: Ahi(10240) Alo(10240) Bhi(10240) Blo(10240) = 40960 B
// ---------------------------------------------------------------------------
__device__ __forceinline__ void issue_stage(
    uint32_t sbase, int stage, int kt, int tid,
    const unsigned char* Aimg, const unsigned char* Bimg,
    long bm, int bn, int K, long loA, long loB)
{
    uint32_t sb0 = sbase + stage * 40960;
#pragma unroll
    for (int i = 0; i < 4; i++) {
        int id = tid + (i << 8);
        int img = id >> 9, row = (id >> 2) & 127, seg = id & 3;
        uint32_t soff = (uint32_t)((img * 128 * TS + row * TS + seg * 8) * 2);
        cpasync16(sb0 + soff,
                  Aimg + ((long)img * loA + (bm + row) * K + kt + seg * 8) * 2);
        cpasync16(sb0 + 20480 + soff,
                  Bimg + ((long)img * loB + (long)(bn + row) * K + kt + seg * 8) * 2);
    }
    asm volatile("cp.async.commit_group;" ::: "memory");
}

// ---------------------------------------------------------------------------
// HMMA GEMM: C[M,N] = epi( A[M,K] @ W[N,K]^T ), pre-split bf16 hi/lo inputs.
// grid=(N/128, M/128), 256 thr (8 warps 2m x 4n), warp tile 64x32, M=TOK.
// epi: 0 = s*acc+b ; 1 = relu(s*acc+b) ; 2 = resid + s*acc+b
// Cf (fp32 out) and/or Chl (bf16 hi/lo out, lo at +TOK*N) may be null.
// ---------------------------------------------------------------------------
__global__ void __launch_bounds__(256, 2) mm_gemm(
    const unsigned char* __restrict__ Aimg, const unsigned char* __restrict__ Bimg,
    const float* __restrict__ sc, const float* __restrict__ bi,
    const float* __restrict__ resid, float* __restrict__ Cf,
    __nv_bfloat16* __restrict__ Chl,
    int N, int K, int epi)
{
    extern __shared__ __align__(16) unsigned char dsm[];
    int tid = threadIdx.x, lane = tid & 31, wid = tid >> 5;
    int wm = (wid & 1) << 6, wn = (wid >> 1) << 5;
    long bm = (long)blockIdx.y << 7;
    int bn = blockIdx.x << 7;
    long loA = (long)TOK * K, loB = (long)N * K;

    float acc[4][4][4] = {};
    uint32_t sbase = smem_u32(dsm);

    issue_stage(sbase, 0, 0, tid, Aimg, Bimg, bm, bn, K, loA, loB);
    int T = K >> 5;
    for (int t = 0; t < T; t++) {
        asm volatile("cp.async.wait_group 0;" ::: "memory");
        __syncthreads();
        if (t + 1 < T)
            issue_stage(sbase, (t + 1) & 1, (t + 1) << 5, tid,
                        Aimg, Bimg, bm, bn, K, loA, loB);
        uint32_t sAh = sbase + (t & 1) * 40960;
        uint32_t sAl = sAh + 10240;
        uint32_t sBh = sAh + 20480;
        uint32_t sBl = sAh + 30720;
#pragma unroll
        for (int kk = 0; kk < 32; kk += 16) {
            uint32_t ah[4][4], al[4][4], bh[2][4], bl[2][4];
#pragma unroll
            for (int mt = 0; mt < 4; mt++)
                ldsm4(ah[mt], a_addr(sAh, wm + mt * 16, kk, lane));
#pragma unroll
            for (int h = 0; h < 2; h++)
                ldsm4(bh[h], b_addr(sBh, wn + h * 16, kk, lane));
#pragma unroll
            for (int mt = 0; mt < 4; mt++)
#pragma unroll
                for (int nt = 0; nt < 4; nt++)
                    mma16816(acc[mt][nt], ah[mt], &bh[nt >> 1][(nt & 1) * 2]);
#pragma unroll
            for (int h = 0; h < 2; h++)
                ldsm4(bl[h], b_addr(sBl, wn + h * 16, kk, lane));
#pragma unroll
            for (int mt = 0; mt < 4; mt++)
#pragma unroll
                for (int nt = 0; nt < 4; nt++)
                    mma16816(acc[mt][nt], ah[mt], &bl[nt >> 1][(nt & 1) * 2]);
#pragma unroll
            for (int mt = 0; mt < 4; mt++)
                ldsm4(al[mt], a_addr(sAl, wm + mt * 16, kk, lane));
#pragma unroll
            for (int mt = 0; mt < 4; mt++)
#pragma unroll
                for (int nt = 0; nt < 4; nt++)
                    mma16816(acc[mt][nt], al[mt], &bh[nt >> 1][(nt & 1) * 2]);
        }
        __syncthreads();
    }

    // epilogue
    int q = lane >> 2, tq = lane & 3;
#pragma unroll
    for (int nt = 0; nt < 4; nt++) {
        int n = bn + wn + nt * 8 + tq * 2;
        float2 s2 = *(const float2*)(sc + n);
        float2 b2 = *(const float2*)(bi + n);
#pragma unroll
        for (int mt = 0; mt < 4; mt++) {
#pragma unroll
            for (int half = 0; half < 2; half++) {
                long m = bm + wm + mt * 16 + q + half * 8;
                float v0 = acc[mt][nt][half * 2 + 0] * s2.x + b2.x;
                float v1 = acc[mt][nt][half * 2 + 1] * s2.y + b2.y;
                if (epi == 1) {
                    v0 = fmaxf(v0, 0.f);
                    v1 = fmaxf(v1, 0.f);
                } else if (epi == 2) {
                    float2 r2 = *(const float2*)(resid + m * N + n);
                    v0 += r2.x;
                    v1 += r2.y;
                }
                if (Cf) {
                    float2 o;
                    o.x = v0; o.y = v1;
                    *(float2*)(Cf + m * N + n) = o;
                }
                if (Chl) {
                    __nv_bfloat16 h0, l0, h1, l1;
                    split_bf16(v0, h0, l0);
                    split_bf16(v1, h1, l1);
                    __nv_bfloat162 hv, lv;
                    hv.x = h0; hv.y = h1;
                    lv.x = l0; lv.y = l1;
                    *(__nv_bfloat162*)(Chl + m * N + n) = hv;
                    *(__nv_bfloat162*)(Chl + (long)TOK * N + m * N + n) = lv;
                }
            }
        }
    }
}

// ---------------------------------------------------------------------------
// dw0: NCHW input -> NHWC,  xA = x + bn(dw3x3(x));  also writes hi/lo image
// ---------------------------------------------------------------------------
__global__ void __launch_bounds__(256) dw0_kernel(
    const float* __restrict__ x, const float* __restrict__ w,
    const float* __restrict__ s, const float* __restrict__ bb)
{
    __shared__ float sx[3][64][29];
    __shared__ float wsm[64][9];
    __shared__ float ssm[64], bsm[64];
    int c0 = blockIdx.x * 64;
    int h = blockIdx.y;
    int b = blockIdx.z;
    int tid = threadIdx.x;

    for (int i = tid; i < 64 * 9; i += 256) {
        int c = i / 9, k = i % 9;
        wsm[c][k] = w[(c0 + c) * 9 + k];
    }
    if (tid < 64) { ssm[tid] = s[c0 + tid]; bsm[tid] = bb[c0 + tid]; }

    for (int i = tid; i < 3 * 64 * 28; i += 256) {
        int row = i / 1792;
        int rem = i % 1792;
        int c = rem / 28, ww = rem % 28;
        int hh = h - 1 + row;
        float v = 0.f;
        if (hh >= 0 && hh < 28)
            v = x[(((long)(b * 256 + c0 + c)) * 28 + hh) * 28 + ww];
        sx[row][c][ww] = v;
    }
    __syncthreads();

    for (int i = tid; i < 64 * 28; i += 256) {
        int cl = i & 63, ww = i >> 6;
        float acc = 0.f;
#pragma unroll
        for (int dy = 0; dy < 3; dy++)
#pragma unroll
            for (int dx = 0; dx < 3; dx++) {
                int w2 = ww + dx - 1;
                if (w2 >= 0 && w2 < 28)
                    acc += wsm[cl][dy * 3 + dx] * sx[dy][cl][w2];
            }
        long t = (long)(b * 28 + h) * 28 + ww;
        float v = sx[1][cl][ww] + ssm[cl] * acc + bsm[cl];
        long o = t * 256 + c0 + cl;
        g_xA[o] = v;
        __nv_bfloat16 hh2, ll2;
        split_bf16(v, hh2, ll2);
        g_xAs[o] = hh2;
        g_xAs[(long)TOK * 256 + o] = ll2;
    }
}

// ---------------------------------------------------------------------------
// dw1: xB = xA + bn(dw3x3(xA));  writes fp32 + hi/lo image
// ---------------------------------------------------------------------------
__global__ void __launch_bounds__(256) dw1_kernel(
    const float* __restrict__ w, const float* __restrict__ s,
    const float* __restrict__ bb)
{
    int t = blockIdx.x;
    int c = threadIdx.x;
    int b = t / 784, rem = t % 784, h = rem / 28, ww = rem % 28;
    float wr[9];
#pragma unroll
    for (int k = 0; k < 9; k++) wr[k] = w[c * 9 + k];
    float acc = 0.f;
#pragma unroll
    for (int dy = 0; dy < 3; dy++) {
        int h2 = h + dy - 1;
        if (h2 < 0 || h2 >= 28) continue;
#pragma unroll
        for (int dx = 0; dx < 3; dx++) {
            int w2 = ww + dx - 1;
            if (w2 < 0 || w2 >= 28) continue;
            acc += wr[dy * 3 + dx] * g_xA[((long)(b * 784 + h2 * 28 + w2)) * 256 + c];
        }
    }
    float v = g_xA[(long)t * 256 + c] + s[c] * acc + bb[c];
    long o = (long)t * 256 + c;
    g_xB[o] = v;
    __nv_bfloat16 hh, ll;
    split_bf16(v, hh, ll);
    g_xBs[o] = hh;
    g_xBs[(long)TOK * 256 + o] = ll;
}

// ---------------------------------------------------------------------------
// dws: 5x5 depthwise conv on q channels of g_qkv -> g_q2
// ---------------------------------------------------------------------------
__global__ void __launch_bounds__(256) dws_kernel(
    const float* __restrict__ w, const float* __restrict__ s,
    const float* __restrict__ bb)
{
    int t = blockIdx.x * 4 + (threadIdx.x >> 6);
    int ch = threadIdx.x & 63;
    int head = ch >> 4, kc = ch & 15;
    int qc = head * 96 + kc;
    int b = t / 784, rem = t % 784, h = rem / 28, ww = rem % 28;
    float acc = 0.f;
#pragma unroll
    for (int dy = 0; dy < 5; dy++) {
        int h2 = h + dy - 2;
        if (h2 < 0 || h2 >= 28) continue;
#pragma unroll
        for (int dx = 0; dx < 5; dx++) {
            int w2 = ww + dx - 2;
            if (w2 < 0 || w2 >= 28) continue;
            acc += w[ch * 25 + dy * 5 + dx] *
                   g_qkv[((long)(b * 784 + h2 * 28 + w2)) * 384 + qc];
        }
    }
    g_q2[(long)t * 64 + ch] = s[ch] * acc + bb[ch];
}

// ---------------------------------------------------------------------------
// per-window attention (7x7 = 49 tokens); writes relu(o) as bf16 hi/lo image
// ---------------------------------------------------------------------------
__global__ void __launch_bounds__(128) attn_kernel(const float* __restrict__ pos)
{
    int wi = blockIdx.x >> 2, wj = blockIdx.x & 3;
    int head = blockIdx.y, b = blockIdx.z;
    int tid = threadIdx.x;

    __shared__ float sq[49 * 17];
    __shared__ float sk[49 * 17];
    __shared__ __align__(16) float sv[49 * 64];
    __shared__ float ss[49 * 50];
    __shared__ int stok[49];

    if (tid < 49) {
        int r = tid;
        stok[r] = b * 784 + (wi * 7 + r / 7) * 28 + wj * 7 + (r % 7);
    }
    __syncthreads();

    for (int i = tid; i < 49 * 16; i += 128) {
        int r = i >> 4, c = i & 15;
        long t = stok[r];
        sq[r * 17 + c] = g_q2[t * 64 + head * 16 + c];
        sk[r * 17 + c] = g_qkv[t * 384 + head * 96 + 16 + c];
    }
    for (int i = tid; i < 49 * 64; i += 128) {
        int r = i >> 6, c = i & 63;
        sv[i] = g_qkv[(long)stok[r] * 384 + head * 96 + 32 + c];
    }
    __syncthreads();

    const float* pe = pos + head * 49 * 49;
    for (int i = tid; i < 49 * 49; i += 128) {
        int qr = i / 49, kr = i % 49;
        float d = 0.f;
#pragma unroll
        for (int c = 0; c < 16; c++)
            d += sq[qr * 17 + c] * sk[kr * 17 + c];
        ss[qr * 50 + kr] = d * 0.25f + pe[i];
    }
    __syncthreads();

    if (tid < 49) {
        float* row = ss + tid * 50;
        float mx = -1e30f;
        for (int k = 0; k < 49; k++) mx = fmaxf(mx, row[k]);
        float sum = 0.f;
        for (int k = 0; k < 49; k++) {
            float e = __expf(row[k] - mx);
            row[k] = e;
            sum += e;
        }
        float inv = 1.f / sum;
        for (int k = 0; k < 49; k++) row[k] *= inv;
    }
    __syncthreads();

    for (int i = tid; i < 49 * 16; i += 128) {
        int qr = i >> 4, d0 = (i & 15) << 2;
        float4 acc = make_float4(0.f, 0.f, 0.f, 0.f);
        for (int k = 0; k < 49; k++) {
            float p = ss[qr * 50 + k];
            float4 v = *(const float4*)&sv[k * 64 + d0];
            acc.x = fmaf(p, v.x, acc.x);
            acc.y = fmaf(p, v.y, acc.y);
            acc.z = fmaf(p, v.z, acc.z);
            acc.w = fmaf(p, v.w, acc.w);
        }
        float r0 = fmaxf(acc.x, 0.f), r1 = fmaxf(acc.y, 0.f);
        float r2 = fmaxf(acc.z, 0.f), r3 = fmaxf(acc.w, 0.f);
        __nv_bfloat16 h0, l0, h1, l1, h2, l2, h3, l3;
        split_bf16(r0, h0, l0);
        split_bf16(r1, h1, l1);
        split_bf16(r2, h2, l2);
        split_bf16(r3, h3, l3);
        long t = stok[qr];
        __nv_bfloat16* ob = g_obs + (long)t * 256 + head * 64 + d0;
        __nv_bfloat162 p01, p23;
        p01.x = h0; p01.y = h1; p23.x = h2; p23.y = h3;
        *(__nv_bfloat162*)(ob) = p01;
        *(__nv_bfloat162*)(ob + 2) = p23;
        p01.x = l0; p01.y = l1; p23.x = l2; p23.y = l3;
        *(__nv_bfloat162*)(ob + (long)TOK * 256) = p01;
        *(__nv_bfloat162*)(ob + (long)TOK * 256 + 2) = p23;
    }
}

// ---------------------------------------------------------------------------
// final transpose: NHWC g_xA -> NCHW d_out
// ---------------------------------------------------------------------------
__global__ void trans_out_kernel(float* __restrict__ out)
{
    __shared__ float tile[32][33];
    int t0 = blockIdx.x * 32, c0 = blockIdx.y * 32, b = blockIdx.z;
    int tx = threadIdx.x, ty = threadIdx.y;
#pragma unroll
    for (int r = 0; r < 4; r++) {
        int t = t0 + ty + r * 8;
        if (t < 784)
            tile[ty + r * 8][tx] = g_xA[((long)(b * 784 + t)) * 256 + c0 + tx];
    }
    __syncthreads();
#pragma unroll
    for (int r = 0; r < 4; r++) {
        int c = c0 + ty + r * 8;
        int t = t0 + tx;
        if (t < 784)
            out[((long)(b * 256 + c)) * 784 + t] = tile[tx][ty + r * 8];
    }
}

// ---------------------------------------------------------------------------
extern "C" void kernel_launch(void* const* d_in, const int* in_sizes, int n_in,
                              void* d_out, int out_size)
{
    const float* in[32];
    for (int i = 0; i < n_in && i < 32; i++) in[i] = (const float*)d_in[i];

    int idw0, idw1, iffn0, iffn1, iqkv, idws, iproj, ipos;
    if (in_sizes[4] > 100000) { // reference-signature order
        idw0 = 1;  iffn0 = 4;  iqkv = 10; idws = 13; iproj = 16;
        ipos = 19; idw1 = 20;  iffn1 = 23;
    } else {                    // setup_inputs dict order
        idw0 = 1;  idw1 = 4;   iffn0 = 7;  iffn1 = 13;
        iqkv = 19; idws = 22;  iproj = 25; ipos = 28;
    }

    const float* x     = in[0];
    const float* dw0_w = in[idw0],  * dw0_s = in[idw0 + 1], * dw0_b = in[idw0 + 2];
    const float* dw1_w = in[idw1],  * dw1_s = in[idw1 + 1], * dw1_b = in[idw1 + 2];
    const float* f0w1 = in[iffn0],     * f0s1 = in[iffn0 + 1], * f0b1 = in[iffn0 + 2];
    const float* f0w2 = in[iffn0 + 3], * f0s2 = in[iffn0 + 4], * f0b2 = in[iffn0 + 5];
    const float* f1w1 = in[iffn1],     * f1s1 = in[iffn1 + 1], * f1b1 = in[iffn1 + 2];
    const float* f1w2 = in[iffn1 + 3], * f1s2 = in[iffn1 + 4], * f1b2 = in[iffn1 + 5];
    const float* qkv_w = in[iqkv],  * qkv_s = in[iqkv + 1],  * qkv_b = in[iqkv + 2];
    const float* dws_w = in[idws],  * dws_s = in[idws + 1],  * dws_b = in[idws + 2];
    const float* proj_w = in[iproj], * proj_s = in[iproj + 1], * proj_b = in[iproj + 2];
    const float* pos = in[ipos];

    float *pxA, *pxB, *pqkv;
    __nv_bfloat16 *pxAs, *phs, *pobs, *pxBs;
    unsigned char* pwtB;
    cudaGetSymbolAddress((void**)&pxA, g_xA);
    cudaGetSymbolAddress((void**)&pxB, g_xB);
    cudaGetSymbolAddress((void**)&pqkv, g_qkv);
    cudaGetSymbolAddress((void**)&pxAs, g_xAs);
    cudaGetSymbolAddress((void**)&phs,  g_hs);
    cudaGetSymbolAddress((void**)&pobs, g_obs);
    cudaGetSymbolAddress((void**)&pxBs, g_xBs);
    cudaGetSymbolAddress((void**)&pwtB, g_wtB);

    const int SMEM_GEMM = 81920;
    cudaFuncSetAttribute(mm_gemm, cudaFuncAttributeMaxDynamicSharedMemorySize,
                         SMEM_GEMM);

    // split weights into bf16 hi/lo images (tiny)
    wconv_kernel<<<(512 * 256 + 255) / 256, 256>>>(f0w1, pwtB + WB_F0W1, 512, 256);
    wconv_kernel<<<(256 * 512 + 255) / 256, 256>>>(f0w2, pwtB + WB_F0W2, 256, 512);
    wconv_kernel<<<(384 * 256 + 255) / 256, 256>>>(qkv_w, pwtB + WB_QKV, 384, 256);
    wconv_kernel<<<(256 * 256 + 255) / 256, 256>>>(proj_w, pwtB + WB_PROJ, 256, 256);
    wconv_kernel<<<(512 * 256 + 255) / 256, 256>>>(f1w1, pwtB + WB_F1W1, 512, 256);
    wconv_kernel<<<(256 * 512 + 255) / 256, 256>>>(f1w2, pwtB + WB_F1W2, 256, 512);

    // 1. xA = x + bn(dw3x3(x))    (NCHW -> NHWC, + hi/lo image)
    dw0_kernel<<<dim3(4, 28, 64), 256>>>(x, dw0_w, dw0_s, dw0_b);

    // 2. ffn0: h(hi/lo only) then xA += ffn (fp32 + hi/lo for qkv)
    mm_gemm<<<dim3(4, 392), 256, SMEM_GEMM>>>(
        (const unsigned char*)pxAs, pwtB + WB_F0W1, f0s1, f0b1, nullptr,
        nullptr, phs, 512, 256, 1);
    mm_gemm<<<dim3(2, 392), 256, SMEM_GEMM>>>(
        (const unsigned char*)phs, pwtB + WB_F0W2, f0s2, f0b2, pxA,
        pxA, pxAs, 256, 512, 2);

    // 3. attention
    mm_gemm<<<dim3(3, 392), 256, SMEM_GEMM>>>(
        (const unsigned char*)pxAs, pwtB + WB_QKV, qkv_s, qkv_b, nullptr,
        pqkv, nullptr, 384, 256, 0);
    dws_kernel<<<TOK / 4, 256>>>(dws_w, dws_s, dws_b);
    attn_kernel<<<dim3(16, 4, 64), 128>>>(pos);
    mm_gemm<<<dim3(2, 392), 256, SMEM_GEMM>>>(
        (const unsigned char*)pobs, pwtB + WB_PROJ, proj_s, proj_b, pxA,
        pxA, nullptr, 256, 256, 2);

    // 4. xB = xA + bn(dw3x3(xA))  (fp32 + hi/lo)
    dw1_kernel<<<TOK, 256>>>(dw1_w, dw1_s, dw1_b);

    // 5. ffn1 (result into xA fp32)
    mm_gemm<<<dim3(4, 392), 256, SMEM_GEMM>>>(
        (const unsigned char*)pxBs, pwtB + WB_F1W1, f1s1, f1b1, nullptr,
        nullptr, phs, 512, 256, 1);
    mm_gemm<<<dim3(2, 392), 256, SMEM_GEMM>>>(
        (const unsigned char*)phs, pwtB + WB_F1W2, f1s2, f1b2, pxB,
        pxA, nullptr, 256, 512, 2);

    // 6. NHWC -> NCHW output
    trans_out_kernel<<<dim3(25, 8, 64), dim3(32, 8)>>>((float*)d_out);
}

// round 11
// speedup vs baseline: 2.0860x; 1.0003x over previous
#include <cuda_runtime.h>
#include <cuda_bf16.h>
#include <cstdint>

// ---------------------------------------------------------------------------
// EfficientViT block. GEMMs via mma.sync bf16 (HMMA) with bf16 hi/lo split.
// Pre-split operands, cp.async double-buffer, 64x64 warp tiles, fused
// NCHW-transpose epilogue on the final GEMM.
// ---------------------------------------------------------------------------

#define TOK   50176

// fp32 scratch
__device__ float g_xA[TOK * 256];
__device__ float g_xB[TOK * 256];
__device__ float g_qkv[TOK * 384];
__device__ float g_q2[TOK * 64];

// bf16 hi/lo activation images (hi at [0], lo at +TOK*C)
__device__ __align__(16) __nv_bfloat16 g_xAs[2 * TOK * 256];
__device__ __align__(16) __nv_bfloat16 g_hs [2 * TOK * 512];
__device__ __align__(16) __nv_bfloat16 g_obs[2 * TOK * 256];
__device__ __align__(16) __nv_bfloat16 g_xBs[2 * TOK * 256];

__device__ __align__(16) unsigned char g_wtB[2752512]; // bf16 hi/lo weight images
#define WB_F0W1 0
#define WB_F0W2 524288
#define WB_QKV  1048576
#define WB_PROJ 1441792
#define WB_F1W1 1703936
#define WB_F1W2 2228224

__device__ __forceinline__ uint32_t smem_u32(const void* p) {
    uint32_t a;
    asm("{ .reg .u64 t; cvta.to.shared.u64 t, %1; cvt.u32.u64 %0, t; }"
        : "=r"(a) : "l"(p));
    return a;
}
__device__ __forceinline__ void cpasync16(uint32_t saddr, const void* g) {
    asm volatile("cp.async.ca.shared.global [%0], [%1], 16;"
                 :: "r"(saddr), "l"(g));
}
__device__ __forceinline__ void ldsm4(uint32_t* r, uint32_t addr) {
    asm volatile("ldmatrix.sync.aligned.m8n8.x4.shared.b16 {%0,%1,%2,%3}, [%4];"
        : "=r"(r[0]), "=r"(r[1]), "=r"(r[2]), "=r"(r[3]) : "r"(addr));
}
__device__ __forceinline__ void mma16816(float* c, const uint32_t* a,
                                         const uint32_t* b) {
    asm volatile(
        "mma.sync.aligned.m16n8k16.row.col.f32.bf16.bf16.f32 "
        "{%0,%1,%2,%3}, {%4,%5,%6,%7}, {%8,%9}, {%0,%1,%2,%3};"
        : "+f"(c[0]), "+f"(c[1]), "+f"(c[2]), "+f"(c[3])
        : "r"(a[0]), "r"(a[1]), "r"(a[2]), "r"(a[3]), "r"(b[0]), "r"(b[1]));
}

// smem tile stride 40 bf16 (80B): 8 consecutive rows hit distinct 128B phases
#define TS 40

__device__ __forceinline__ uint32_t a_addr(uint32_t base, int m, int k, int lane) {
    int g = lane >> 3, r = lane & 7;
    return base + ((m + ((g & 1) << 3) + r) * TS + k + ((g >> 1) << 3)) * 2;
}
__device__ __forceinline__ uint32_t b_addr(uint32_t base, int n, int k, int lane) {
    int g = lane >> 3, r = lane & 7;
    return base + ((n + ((g >> 1) << 3) + r) * TS + k + ((g & 1) << 3)) * 2;
}

__device__ __forceinline__ void split_bf16(float v, __nv_bfloat16& h,
                                           __nv_bfloat16& l) {
    h = __float2bfloat16(v);
    l = __float2bfloat16(v - __bfloat162float(h));
}

// ---------------------------------------------------------------------------
// All-weights split in ONE launch: 6 fp32 [N,K] -> hi/lo bf16 images in g_wtB
// ---------------------------------------------------------------------------
__global__ void wconv_all(const float* __restrict__ w0, const float* __restrict__ w1,
                          const float* __restrict__ w2, const float* __restrict__ w3,
                          const float* __restrict__ w4, const float* __restrict__ w5,
                          unsigned char* __restrict__ dst) {
    long i = (long)blockIdx.x * 256 + threadIdx.x;
    if (i >= 688128) return;
    const long cum[7] = {0, 131072, 262144, 360448, 425984, 557056, 688128};
    const float* srcs[6] = {w0, w1, w2, w3, w4, w5};
    int s = 0;
    while (i >= cum[s + 1]) s++;
    long j = i - cum[s];
    long nk = cum[s + 1] - cum[s];
    __nv_bfloat16 h, l;
    split_bf16(srcs[s][j], h, l);
    __nv_bfloat16* base = (__nv_bfloat16*)(dst + cum[s] * 4);
    base[j] = h;
    base[nk + j] = l;
}

// ---------------------------------------------------------------------------
// stage loader: A/B hi+lo tiles [128][32] bf16 each -> smem stage via cp.async
// stage layout: Ahi(10240) Alo(10240) Bhi(10240) Blo(10240) = 40960 B
// 128 threads, 1024 ids, 2 cp.async each.
// ---------------------------------------------------------------------------
__device__ __forceinline__ void issue_stage(
    uint32_t sbase, int stage, int kt, int tid,
    const unsigned char* Aimg, const unsigned char* Bimg,
    long bm, int bn, int K, long loA, long loB)
{
    uint32_t sb0 = sbase + stage * 40960;
#pragma unroll
    for (int i = 0; i < 8; i++) {
        int id = tid + (i << 7);
        int img = id >> 9, row = (id >> 2) & 127, seg = id & 3;
        uint32_t soff = (uint32_t)((img * 128 * TS + row * TS + seg * 8) * 2);
        cpasync16(sb0 + soff,
                  Aimg + ((long)img * loA + (bm + row) * K + kt + seg * 8) * 2);
        cpasync16(sb0 + 20480 + soff,
                  Bimg + ((long)img * loB + (long)(bn + row) * K + kt + seg * 8) * 2);
    }
    asm volatile("cp.async.commit_group;" ::: "memory");
}

// ---------------------------------------------------------------------------
// HMMA GEMM: C[M,N] = epi( A[M,K] @ W[N,K]^T ), pre-split bf16 hi/lo inputs.
// grid=(N/128, M/128), 128 thr (4 warps 2m x 2n), warp tile 64x64, M=TOK.
// epi: 0 = s*acc+b ; 1 = relu ; 2 = resid+ ; 3 = resid+ then NCHW transpose out
// ---------------------------------------------------------------------------
__global__ void __launch_bounds__(128, 2) mm_gemm(
    const unsigned char* __restrict__ Aimg, const unsigned char* __restrict__ Bimg,
    const float* __restrict__ sc, const float* __restrict__ bi,
    const float* __restrict__ resid, float* __restrict__ Cf,
    __nv_bfloat16* __restrict__ Chl,
    int N, int K, int epi)
{
    extern __shared__ __align__(16) unsigned char dsm[];
    int tid = threadIdx.x, lane = tid & 31, wid = tid >> 5;
    int wm = (wid & 1) << 6, wn = (wid >> 1) << 6;
    long bm = (long)blockIdx.y << 7;
    int bn = blockIdx.x << 7;
    long loA = (long)TOK * K, loB = (long)N * K;

    float acc[4][8][4] = {};
    uint32_t sbase = smem_u32(dsm);

    issue_stage(sbase, 0, 0, tid, Aimg, Bimg, bm, bn, K, loA, loB);
    int T = K >> 5;
    for (int t = 0; t < T; t++) {
        asm volatile("cp.async.wait_group 0;" ::: "memory");
        __syncthreads();
        if (t + 1 < T)
            issue_stage(sbase, (t + 1) & 1, (t + 1) << 5, tid,
                        Aimg, Bimg, bm, bn, K, loA, loB);
        uint32_t sAh = sbase + (t & 1) * 40960;
        uint32_t sAl = sAh + 10240;
        uint32_t sBh = sAh + 20480;
        uint32_t sBl = sAh + 30720;
#pragma unroll
        for (int kk = 0; kk < 32; kk += 16) {
            uint32_t ah[4][4], al[4][4], bh[4][4], bl[4][4];
#pragma unroll
            for (int mt = 0; mt < 4; mt++)
                ldsm4(ah[mt], a_addr(sAh, wm + mt * 16, kk, lane));
#pragma unroll
            for (int h = 0; h < 4; h++)
                ldsm4(bh[h], b_addr(sBh, wn + h * 16, kk, lane));
#pragma unroll
            for (int mt = 0; mt < 4; mt++)
#pragma unroll
                for (int nt = 0; nt < 8; nt++)
                    mma16816(acc[mt][nt], ah[mt], &bh[nt >> 1][(nt & 1) * 2]);
#pragma unroll
            for (int h = 0; h < 4; h++)
                ldsm4(bl[h], b_addr(sBl, wn + h * 16, kk, lane));
#pragma unroll
            for (int mt = 0; mt < 4; mt++)
#pragma unroll
                for (int nt = 0; nt < 8; nt++)
                    mma16816(acc[mt][nt], ah[mt], &bl[nt >> 1][(nt & 1) * 2]);
#pragma unroll
            for (int mt = 0; mt < 4; mt++)
                ldsm4(al[mt], a_addr(sAl, wm + mt * 16, kk, lane));
#pragma unroll
            for (int mt = 0; mt < 4; mt++)
#pragma unroll
                for (int nt = 0; nt < 8; nt++)
                    mma16816(acc[mt][nt], al[mt], &bh[nt >> 1][(nt & 1) * 2]);
        }
        __syncthreads();
    }

    int q = lane >> 2, tq = lane & 3;

    if (epi == 3) {
        // fused scale/bias/residual + NCHW transpose-out via smem
        float* tile = (float*)dsm;       // [128][129] fp32
#pragma unroll
        for (int nt = 0; nt < 8; nt++) {
            int nl = wn + nt * 8 + tq * 2;
            int n = bn + nl;
            float2 s2 = *(const float2*)(sc + n);
            float2 b2 = *(const float2*)(bi + n);
#pragma unroll
            for (int mt = 0; mt < 4; mt++) {
#pragma unroll
                for (int half = 0; half < 2; half++) {
                    int row = wm + mt * 16 + q + half * 8;
                    long m = bm + row;
                    float2 r2 = *(const float2*)(resid + m * N + n);
                    tile[row * 129 + nl]     = acc[mt][nt][half * 2 + 0] * s2.x + b2.x + r2.x;
                    tile[row * 129 + nl + 1] = acc[mt][nt][half * 2 + 1] * s2.y + b2.y + r2.y;
                }
            }
        }
        __syncthreads();
#pragma unroll
        for (int chunk = 0; chunk < 4; chunk++) {
            int row = chunk * 32 + lane;
            long tk = bm + row;
            int b = (int)(tk / 784), tr = (int)(tk % 784);
            float* obase = Cf + ((long)(b * 256 + bn)) * 784 + tr;
            for (int ci = 0; ci < 32; ci++) {
                int c = wid * 32 + ci;
                obase[(long)c * 784] = tile[row * 129 + c];
            }
        }
        return;
    }

#pragma unroll
    for (int nt = 0; nt < 8; nt++) {
        int n = bn + wn + nt * 8 + tq * 2;
        float2 s2 = *(const float2*)(sc + n);
        float2 b2 = *(const float2*)(bi + n);
#pragma unroll
        for (int mt = 0; mt < 4; mt++) {
#pragma unroll
            for (int half = 0; half < 2; half++) {
                long m = bm + wm + mt * 16 + q + half * 8;
                float v0 = acc[mt][nt][half * 2 + 0] * s2.x + b2.x;
                float v1 = acc[mt][nt][half * 2 + 1] * s2.y + b2.y;
                if (epi == 1) {
                    v0 = fmaxf(v0, 0.f);
                    v1 = fmaxf(v1, 0.f);
                } else if (epi == 2) {
                    float2 r2 = *(const float2*)(resid + m * N + n);
                    v0 += r2.x;
                    v1 += r2.y;
                }
                if (Cf) {
                    float2 o;
                    o.x = v0; o.y = v1;
                    *(float2*)(Cf + m * N + n) = o;
                }
                if (Chl) {
                    __nv_bfloat16 h0, l0, h1, l1;
                    split_bf16(v0, h0, l0);
                    split_bf16(v1, h1, l1);
                    __nv_bfloat162 hv, lv;
                    hv.x = h0; hv.y = h1;
                    lv.x = l0; lv.y = l1;
                    *(__nv_bfloat162*)(Chl + m * N + n) = hv;
                    *(__nv_bfloat162*)(Chl + (long)TOK * N + m * N + n) = lv;
                }
            }
        }
    }
}

// ---------------------------------------------------------------------------
// dw0: NCHW input -> NHWC,  xA = x + bn(dw3x3(x));  also writes hi/lo image
// ---------------------------------------------------------------------------
__global__ void __launch_bounds__(256) dw0_kernel(
    const float* __restrict__ x, const float* __restrict__ w,
    const float* __restrict__ s, const float* __restrict__ bb)
{
    __shared__ float sx[3][64][29];
    __shared__ float wsm[64][9];
    __shared__ float ssm[64], bsm[64];
    int c0 = blockIdx.x * 64;
    int h = blockIdx.y;
    int b = blockIdx.z;
    int tid = threadIdx.x;

    for (int i = tid; i < 64 * 9; i += 256) {
        int c = i / 9, k = i % 9;
        wsm[c][k] = w[(c0 + c) * 9 + k];
    }
    if (tid < 64) { ssm[tid] = s[c0 + tid]; bsm[tid] = bb[c0 + tid]; }

    for (int i = tid; i < 3 * 64 * 28; i += 256) {
        int row = i / 1792;
        int rem = i % 1792;
        int c = rem / 28, ww = rem % 28;
        int hh = h - 1 + row;
        float v = 0.f;
        if (hh >= 0 && hh < 28)
            v = x[(((long)(b * 256 + c0 + c)) * 28 + hh) * 28 + ww];
        sx[row][c][ww] = v;
    }
    __syncthreads();

    for (int i = tid; i < 64 * 28; i += 256) {
        int cl = i & 63, ww = i >> 6;
        float acc = 0.f;
#pragma unroll
        for (int dy = 0; dy < 3; dy++)
#pragma unroll
            for (int dx = 0; dx < 3; dx++) {
                int w2 = ww + dx - 1;
                if (w2 >= 0 && w2 < 28)
                    acc += wsm[cl][dy * 3 + dx] * sx[dy][cl][w2];
            }
        long t = (long)(b * 28 + h) * 28 + ww;
        float v = sx[1][cl][ww] + ssm[cl] * acc + bsm[cl];
        long o = t * 256 + c0 + cl;
        g_xA[o] = v;
        __nv_bfloat16 hh2, ll2;
        split_bf16(v, hh2, ll2);
        g_xAs[o] = hh2;
        g_xAs[(long)TOK * 256 + o] = ll2;
    }
}

// ---------------------------------------------------------------------------
// dw1: xB = xA + bn(dw3x3(xA));  writes fp32 + hi/lo image
// ---------------------------------------------------------------------------
__global__ void __launch_bounds__(256) dw1_kernel(
    const float* __restrict__ w, const float* __restrict__ s,
    const float* __restrict__ bb)
{
    int t = blockIdx.x;
    int c = threadIdx.x;
    int b = t / 784, rem = t % 784, h = rem / 28, ww = rem % 28;
    float wr[9];
#pragma unroll
    for (int k = 0; k < 9; k++) wr[k] = w[c * 9 + k];
    float acc = 0.f;
#pragma unroll
    for (int dy = 0; dy < 3; dy++) {
        int h2 = h + dy - 1;
        if (h2 < 0 || h2 >= 28) continue;
#pragma unroll
        for (int dx = 0; dx < 3; dx++) {
            int w2 = ww + dx - 1;
            if (w2 < 0 || w2 >= 28) continue;
            acc += wr[dy * 3 + dx] * g_xA[((long)(b * 784 + h2 * 28 + w2)) * 256 + c];
        }
    }
    float v = g_xA[(long)t * 256 + c] + s[c] * acc + bb[c];
    long o = (long)t * 256 + c;
    g_xB[o] = v;
    __nv_bfloat16 hh, ll;
    split_bf16(v, hh, ll);
    g_xBs[o] = hh;
    g_xBs[(long)TOK * 256 + o] = ll;
}

// ---------------------------------------------------------------------------
// dws: 5x5 depthwise conv on q channels of g_qkv -> g_q2
// ---------------------------------------------------------------------------
__global__ void __launch_bounds__(256) dws_kernel(
    const float* __restrict__ w, const float* __restrict__ s,
    const float* __restrict__ bb)
{
    int t = blockIdx.x * 4 + (threadIdx.x >> 6);
    int ch = threadIdx.x & 63;
    int head = ch >> 4, kc = ch & 15;
    int qc = head * 96 + kc;
    int b = t / 784, rem = t % 784, h = rem / 28, ww = rem % 28;
    float acc = 0.f;
#pragma unroll
    for (int dy = 0; dy < 5; dy++) {
        int h2 = h + dy - 2;
        if (h2 < 0 || h2 >= 28) continue;
#pragma unroll
        for (int dx = 0; dx < 5; dx++) {
            int w2 = ww + dx - 2;
            if (w2 < 0 || w2 >= 28) continue;
            acc += w[ch * 25 + dy * 5 + dx] *
                   g_qkv[((long)(b * 784 + h2 * 28 + w2)) * 384 + qc];
        }
    }
    g_q2[(long)t * 64 + ch] = s[ch] * acc + bb[ch];
}

// ---------------------------------------------------------------------------
// per-window attention (7x7 = 49 tokens); writes relu(o) as bf16 hi/lo image
// ---------------------------------------------------------------------------
__global__ void __launch_bounds__(128) attn_kernel(const float* __restrict__ pos)
{
    int wi = blockIdx.x >> 2, wj = blockIdx.x & 3;
    int head = blockIdx.y, b = blockIdx.z;
    int tid = threadIdx.x;

    __shared__ float sq[49 * 17];
    __shared__ float sk[49 * 17];
    __shared__ __align__(16) float sv[49 * 64];
    __shared__ float ss[49 * 50];
    __shared__ int stok[49];

    if (tid < 49) {
        int r = tid;
        stok[r] = b * 784 + (wi * 7 + r / 7) * 28 + wj * 7 + (r % 7);
    }
    __syncthreads();

    for (int i = tid; i < 49 * 16; i += 128) {
        int r = i >> 4, c = i & 15;
        long t = stok[r];
        sq[r * 17 + c] = g_q2[t * 64 + head * 16 + c];
        sk[r * 17 + c] = g_qkv[t * 384 + head * 96 + 16 + c];
    }
    for (int i = tid; i < 49 * 64; i += 128) {
        int r = i >> 6, c = i & 63;
        sv[i] = g_qkv[(long)stok[r] * 384 + head * 96 + 32 + c];
    }
    __syncthreads();

    const float* pe = pos + head * 49 * 49;
    for (int i = tid; i < 49 * 49; i += 128) {
        int qr = i / 49, kr = i % 49;
        float d = 0.f;
#pragma unroll
        for (int c = 0; c < 16; c++)
            d += sq[qr * 17 + c] * sk[kr * 17 + c];
        ss[qr * 50 + kr] = d * 0.25f + pe[i];
    }
    __syncthreads();

    {   // softmax, 2 threads per row + shfl combine (all 128 threads in shfls)
        int r = tid >> 1, hf = tid & 1;
        bool act = r < 49;
        float* row = ss + (act ? r : 0) * 50;
        int k0 = hf ? 25 : 0, cnt = hf ? 24 : 25;
        float mx = -1e30f;
        for (int k = 0; k < cnt; k++) mx = fmaxf(mx, row[k0 + k]);
        mx = fmaxf(mx, __shfl_xor_sync(0xffffffffu, mx, 1));
        float ev[25];
        float sum = 0.f;
        for (int k = 0; k < cnt; k++) {
            ev[k] = __expf(row[k0 + k] - mx);
            sum += ev[k];
        }
        sum += __shfl_xor_sync(0xffffffffu, sum, 1);
        float inv = 1.f / sum;
        if (act)
            for (int k = 0; k < cnt; k++) row[k0 + k] = ev[k] * inv;
    }
    __syncthreads();

    for (int i = tid; i < 49 * 16; i += 128) {
        int qr = i >> 4, d0 = (i & 15) << 2;
        float4 acc = make_float4(0.f, 0.f, 0.f, 0.f);
        for (int k = 0; k < 49; k++) {
            float p = ss[qr * 50 + k];
            float4 v = *(const float4*)&sv[k * 64 + d0];
            acc.x = fmaf(p, v.x, acc.x);
            acc.y = fmaf(p, v.y, acc.y);
            acc.z = fmaf(p, v.z, acc.z);
            acc.w = fmaf(p, v.w, acc.w);
        }
        float r0 = fmaxf(acc.x, 0.f), r1 = fmaxf(acc.y, 0.f);
        float r2 = fmaxf(acc.z, 0.f), r3 = fmaxf(acc.w, 0.f);
        __nv_bfloat16 h0, l0, h1, l1, h2, l2, h3, l3;
        split_bf16(r0, h0, l0);
        split_bf16(r1, h1, l1);
        split_bf16(r2, h2, l2);
        split_bf16(r3, h3, l3);
        long t = stok[qr];
        __nv_bfloat16* ob = g_obs + (long)t * 256 + head * 64 + d0;
        __nv_bfloat162 p01, p23;
        p01.x = h0; p01.y = h1; p23.x = h2; p23.y = h3;
        *(__nv_bfloat162*)(ob) = p01;
        *(__nv_bfloat162*)(ob + 2) = p23;
        p01.x = l0; p01.y = l1; p23.x = l2; p23.y = l3;
        *(__nv_bfloat162*)(ob + (long)TOK * 256) = p01;
        *(__nv_bfloat162*)(ob + (long)TOK * 256 + 2) = p23;
    }
}

// ---------------------------------------------------------------------------
extern "C" void kernel_launch(void* const* d_in, const int* in_sizes, int n_in,
                              void* d_out, int out_size)
{
    const float* in[32];
    for (int i = 0; i < n_in && i < 32; i++) in[i] = (const float*)d_in[i];

    int idw0, idw1, iffn0, iffn1, iqkv, idws, iproj, ipos;
    if (in_sizes[4] > 100000) { // reference-signature order
        idw0 = 1;  iffn0 = 4;  iqkv = 10; idws = 13; iproj = 16;
        ipos = 19; idw1 = 20;  iffn1 = 23;
    } else {                    // setup_inputs dict order
        idw0 = 1;  idw1 = 4;   iffn0 = 7;  iffn1 = 13;
        iqkv = 19; idws = 22;  iproj = 25; ipos = 28;
    }

    const float* x     = in[0];
    const float* dw0_w = in[idw0],  * dw0_s = in[idw0 + 1], * dw0_b = in[idw0 + 2];
    const float* dw1_w = in[idw1],  * dw1_s = in[idw1 + 1], * dw1_b = in[idw1 + 2];
    const float* f0w1 = in[iffn0],     * f0s1 = in[iffn0 + 1], * f0b1 = in[iffn0 + 2];
    const float* f0w2 = in[iffn0 + 3], * f0s2 = in[iffn0 + 4], * f0b2 = in[iffn0 + 5];
    const float* f1w1 = in[iffn1],     * f1s1 = in[iffn1 + 1], * f1b1 = in[iffn1 + 2];
    const float* f1w2 = in[iffn1 + 3], * f1s2 = in[iffn1 + 4], * f1b2 = in[iffn1 + 5];
    const float* qkv_w = in[iqkv],  * qkv_s = in[iqkv + 1],  * qkv_b = in[iqkv + 2];
    const float* dws_w = in[idws],  * dws_s = in[idws + 1],  * dws_b = in[idws + 2];
    const float* proj_w = in[iproj], * proj_s = in[iproj + 1], * proj_b = in[iproj + 2];
    const float* pos = in[ipos];

    float *pxA, *pxB, *pqkv;
    __nv_bfloat16 *pxAs, *phs, *pobs, *pxBs;
    unsigned char* pwtB;
    cudaGetSymbolAddress((void**)&pxA, g_xA);
    cudaGetSymbolAddress((void**)&pxB, g_xB);
    cudaGetSymbolAddress((void**)&pqkv, g_qkv);
    cudaGetSymbolAddress((void**)&pxAs, g_xAs);
    cudaGetSymbolAddress((void**)&phs,  g_hs);
    cudaGetSymbolAddress((void**)&pobs, g_obs);
    cudaGetSymbolAddress((void**)&pxBs, g_xBs);
    cudaGetSymbolAddress((void**)&pwtB, g_wtB);

    const int SMEM_GEMM = 81920;
    cudaFuncSetAttribute(mm_gemm, cudaFuncAttributeMaxDynamicSharedMemorySize,
                         SMEM_GEMM);

    // split all weights into bf16 hi/lo images (one launch)
    wconv_all<<<(688128 + 255) / 256, 256>>>(f0w1, f0w2, qkv_w, proj_w, f1w1,
                                             f1w2, pwtB);

    // 1. xA = x + bn(dw3x3(x))    (NCHW -> NHWC, + hi/lo image)
    dw0_kernel<<<dim3(4, 28, 64), 256>>>(x, dw0_w, dw0_s, dw0_b);

    // 2. ffn0: h(hi/lo only) then xA += ffn (fp32 + hi/lo for qkv)
    mm_gemm<<<dim3(4, 392), 128, SMEM_GEMM>>>(
        (const unsigned char*)pxAs, pwtB + WB_F0W1, f0s1, f0b1, nullptr,
        nullptr, phs, 512, 256, 1);
    mm_gemm<<<dim3(2, 392), 128, SMEM_GEMM>>>(
        (const unsigned char*)phs, pwtB + WB_F0W2, f0s2, f0b2, pxA,
        pxA, pxAs, 256, 512, 2);

    // 3. attention
    mm_gemm<<<dim3(3, 392), 128, SMEM_GEMM>>>(
        (const unsigned char*)pxAs, pwtB + WB_QKV, qkv_s, qkv_b, nullptr,
        pqkv, nullptr, 384, 256, 0);
    dws_kernel<<<TOK / 4, 256>>>(dws_w, dws_s, dws_b);
    attn_kernel<<<dim3(16, 4, 64), 128>>>(pos);
    mm_gemm<<<dim3(2, 392), 128, SMEM_GEMM>>>(
        (const unsigned char*)pobs, pwtB + WB_PROJ, proj_s, proj_b, pxA,
        pxA, nullptr, 256, 256, 2);

    // 4. xB = xA + bn(dw3x3(xA))  (fp32 + hi/lo)
    dw1_kernel<<<TOK, 256>>>(dw1_w, dw1_s, dw1_b);

    // 5. ffn1: h then FINAL gemm writes d_out in NCHW directly (epi=3)
    mm_gemm<<<dim3(4, 392), 128, SMEM_GEMM>>>(
        (const unsigned char*)pxBs, pwtB + WB_F1W1, f1s1, f1b1, nullptr,
        nullptr, phs, 512, 256, 1);
    mm_gemm<<<dim3(2, 392), 128, SMEM_GEMM>>>(
        (const unsigned char*)phs, pwtB + WB_F1W2, f1s2, f1b2, pxB,
        (float*)d_out, nullptr, 256, 512, 3);
}

// round 12
// speedup vs baseline: 2.3081x; 1.1064x over previous
#include <cuda_runtime.h>
#include <cuda_bf16.h>
#include <cstdint>

// ---------------------------------------------------------------------------
// EfficientViT block. HMMA mma.sync bf16 hi/lo-split GEMMs.
// Activations/weights pre-split into TILE-BLOCKED padded bf16 images
// ([128 rows x 32 k] per tile, stride 40, hi+lo adjacent = 20480 B blocks),
// streamed into smem with cp.async.bulk + mbarrier (2 instr/stage).
// ---------------------------------------------------------------------------

#define TOK   50176

// fp32 scratch
__device__ float g_xA[TOK * 256];
__device__ float g_xB[TOK * 256];
__device__ float g_qkv[TOK * 384];
__device__ float g_q2[TOK * 64];

// blocked hi/lo bf16 images: 5 bytes/elem (2+2 data, 1 padding amortized)
__device__ __align__(16) unsigned char g_xAs[TOK * 256 * 5];
__device__ __align__(16) unsigned char g_hs [TOK * 512 * 5];
__device__ __align__(16) unsigned char g_obs[TOK * 256 * 5];
__device__ __align__(16) unsigned char g_xBs[TOK * 256 * 5];
__device__ __align__(16) unsigned char g_wtB[3440640];

// weight-image byte offsets (blocked layout, N*K*5 bytes each)
#define WB_F0W1 0
#define WB_F0W2 655360
#define WB_QKV  1310720
#define WB_PROJ 1802240
#define WB_F1W1 2129920
#define WB_F1W2 2785280

__device__ __forceinline__ uint32_t smem_u32(const void* p) {
    uint32_t a;
    asm("{ .reg .u64 t; cvta.to.shared.u64 t, %1; cvt.u32.u64 %0, t; }"
        : "=r"(a) : "l"(p));
    return a;
}
__device__ __forceinline__ void ldsm4(uint32_t* r, uint32_t addr) {
    asm volatile("ldmatrix.sync.aligned.m8n8.x4.shared.b16 {%0,%1,%2,%3}, [%4];"
        : "=r"(r[0]), "=r"(r[1]), "=r"(r[2]), "=r"(r[3]) : "r"(addr));
}
__device__ __forceinline__ void mma16816(float* c, const uint32_t* a,
                                         const uint32_t* b) {
    asm volatile(
        "mma.sync.aligned.m16n8k16.row.col.f32.bf16.bf16.f32 "
        "{%0,%1,%2,%3}, {%4,%5,%6,%7}, {%8,%9}, {%0,%1,%2,%3};"
        : "+f"(c[0]), "+f"(c[1]), "+f"(c[2]), "+f"(c[3])
        : "r"(a[0]), "r"(a[1]), "r"(a[2]), "r"(a[3]), "r"(b[0]), "r"(b[1]));
}

#define MBARRIER_INIT(mbar_addr, count) \
    asm volatile("mbarrier.init.shared.b64 [%0], %1;" \
        :: "r"((uint32_t)(mbar_addr)), "r"((uint32_t)(count)) : "memory")
#define MBARRIER_EXPECT_TX(mbar_addr, tx_bytes) \
    asm volatile("mbarrier.arrive.expect_tx.shared.b64 _, [%0], %1;" \
        :: "r"((uint32_t)(mbar_addr)), "r"((uint32_t)(tx_bytes)) : "memory")
#define MBARRIER_WAIT_PARITY(mbar_addr, parity) do { \
    uint32_t _mbar = (uint32_t)(mbar_addr); \
    uint32_t _par = (uint32_t)(parity); \
    uint32_t _done; \
    asm volatile( \
        "{\n\t.reg .pred p;\n\t" \
        "mbarrier.try_wait.parity.acquire.cta.shared::cta.b64 p, [%1], %2;\n\t" \
        "selp.b32 %0, 1, 0, p;\n\t}" \
        : "=r"(_done) : "r"(_mbar), "r"(_par) : "memory"); \
    if (!_done) { \
        asm volatile( \
            "{\n\t.reg .pred P1;\n\t" \
            "WAIT_LOOP_%=:\n\t" \
            "mbarrier.try_wait.parity.acquire.cta.shared::cta.b64 P1, [%0], %1, 0x989680;\n\t" \
            "@P1 bra.uni WAIT_DONE_%=;\n\t" \
            "bra.uni WAIT_LOOP_%=;\n\t" \
            "WAIT_DONE_%=:\n\t}" \
            :: "r"(_mbar), "r"(_par) : "memory"); \
    } \
} while (0)

__device__ __forceinline__ void bulkcp(uint32_t dst, const void* src,
                                       uint32_t mbar) {
    asm volatile(
        "cp.async.bulk.shared::cta.global.mbarrier::complete_tx::bytes "
        "[%0], [%1], %2, [%3];"
        :: "r"(dst), "l"(src), "r"(20480u), "r"(mbar) : "memory");
}

// blocked-image byte offset of (row, col) hi element; lo at +10240
__device__ __forceinline__ long img_off(long row, int col, int Kd) {
    return ((row >> 7) * (Kd >> 5) + (col >> 5)) * 20480L +
           (row & 127) * 80 + (col & 31) * 2;
}

// smem tile stride 40 bf16 (80B): conflict-free ldmatrix phases
#define TS 40
__device__ __forceinline__ uint32_t a_addr(uint32_t base, int m, int k, int lane) {
    int g = lane >> 3, r = lane & 7;
    return base + ((m + ((g & 1) << 3) + r) * TS + k + ((g >> 1) << 3)) * 2;
}
__device__ __forceinline__ uint32_t b_addr(uint32_t base, int n, int k, int lane) {
    int g = lane >> 3, r = lane & 7;
    return base + ((n + ((g >> 1) << 3) + r) * TS + k + ((g & 1) << 3)) * 2;
}

__device__ __forceinline__ void split_bf16(float v, __nv_bfloat16& h,
                                           __nv_bfloat16& l) {
    h = __float2bfloat16(v);
    l = __float2bfloat16(v - __bfloat162float(h));
}

// ---------------------------------------------------------------------------
// All-weights split into blocked images, one launch
// ---------------------------------------------------------------------------
__global__ void wconv_all(const float* __restrict__ w0, const float* __restrict__ w1,
                          const float* __restrict__ w2, const float* __restrict__ w3,
                          const float* __restrict__ w4, const float* __restrict__ w5,
                          unsigned char* __restrict__ dst) {
    long i = (long)blockIdx.x * 256 + threadIdx.x;
    if (i >= 688128) return;
    const long cum[7] = {0, 131072, 262144, 360448, 425984, 557056, 688128};
    const long ob[6] = {WB_F0W1, WB_F0W2, WB_QKV, WB_PROJ, WB_F1W1, WB_F1W2};
    const int Ks[6] = {256, 512, 256, 256, 256, 512};
    const float* srcs[6] = {w0, w1, w2, w3, w4, w5};
    int s = 0;
    while (i >= cum[s + 1]) s++;
    long j = i - cum[s];
    int K = Ks[s];
    long n = j / K;
    int k = (int)(j % K);
    __nv_bfloat16 h, l;
    split_bf16(srcs[s][j], h, l);
    long off = ob[s] + img_off(n, k, K);
    *(__nv_bfloat16*)(dst + off) = h;
    *(__nv_bfloat16*)(dst + off + 10240) = l;
}

// ---------------------------------------------------------------------------
// HMMA GEMM: C[M,N] = epi( A[M,K] @ W[N,K]^T ), blocked hi/lo bf16 images.
// grid=(N/128, M/128), 256 thr (8 warps 2m x 4n), warp tile 64x32.
// epi: 0 plain ; 1 relu ; 2 resid+ ; 3 resid+ & NCHW transpose out
// ---------------------------------------------------------------------------
__global__ void __launch_bounds__(256, 2) mm_gemm(
    const unsigned char* __restrict__ Aimg, const unsigned char* __restrict__ Bimg,
    const float* __restrict__ sc, const float* __restrict__ bi,
    const float* __restrict__ resid, float* __restrict__ Cf,
    unsigned char* __restrict__ Chl,
    int N, int K, int epi)
{
    extern __shared__ __align__(128) unsigned char dsm[];
    __shared__ __align__(8) unsigned long long mbars[2];
    int tid = threadIdx.x, lane = tid & 31, wid = tid >> 5;
    int wm = (wid & 1) << 6, wn = (wid >> 1) << 5;
    long bm = (long)blockIdx.y << 7;
    int bn = blockIdx.x << 7;
    int KT = K >> 5;

    float acc[4][4][4] = {};
    uint32_t sbase = smem_u32(dsm);
    uint32_t mb = smem_u32(mbars);

    if (tid == 0) {
        MBARRIER_INIT(mb, 1);
        MBARRIER_INIT(mb + 8, 1);
    }
    __syncthreads();

    const unsigned char* Ab = Aimg + (long)blockIdx.y * KT * 20480;
    const unsigned char* Bb = Bimg + (long)blockIdx.x * KT * 20480;

    if (tid == 0) {
        MBARRIER_EXPECT_TX(mb, 40960);
        bulkcp(sbase, Ab, mb);
        bulkcp(sbase + 20480, Bb, mb);
        if (KT > 1) {
            MBARRIER_EXPECT_TX(mb + 8, 40960);
            bulkcp(sbase + 40960, Ab + 20480, mb + 8);
            bulkcp(sbase + 61440, Bb + 20480, mb + 8);
        }
    }

    for (int t = 0; t < KT; t++) {
        MBARRIER_WAIT_PARITY(mb + (t & 1) * 8, (t >> 1) & 1);
        uint32_t sAh = sbase + (t & 1) * 40960;
        uint32_t sAl = sAh + 10240;
        uint32_t sBh = sAh + 20480;
        uint32_t sBl = sAh + 30720;
#pragma unroll
        for (int kk = 0; kk < 32; kk += 16) {
            uint32_t ah[4][4], al[4][4], bh[2][4], bl[2][4];
#pragma unroll
            for (int mt = 0; mt < 4; mt++)
                ldsm4(ah[mt], a_addr(sAh, wm + mt * 16, kk, lane));
#pragma unroll
            for (int h = 0; h < 2; h++)
                ldsm4(bh[h], b_addr(sBh, wn + h * 16, kk, lane));
#pragma unroll
            for (int mt = 0; mt < 4; mt++)
#pragma unroll
                for (int nt = 0; nt < 4; nt++)
                    mma16816(acc[mt][nt], ah[mt], &bh[nt >> 1][(nt & 1) * 2]);
#pragma unroll
            for (int h = 0; h < 2; h++)
                ldsm4(bl[h], b_addr(sBl, wn + h * 16, kk, lane));
#pragma unroll
            for (int mt = 0; mt < 4; mt++)
#pragma unroll
                for (int nt = 0; nt < 4; nt++)
                    mma16816(acc[mt][nt], ah[mt], &bl[nt >> 1][(nt & 1) * 2]);
#pragma unroll
            for (int mt = 0; mt < 4; mt++)
                ldsm4(al[mt], a_addr(sAl, wm + mt * 16, kk, lane));
#pragma unroll
            for (int mt = 0; mt < 4; mt++)
#pragma unroll
                for (int nt = 0; nt < 4; nt++)
                    mma16816(acc[mt][nt], al[mt], &bh[nt >> 1][(nt & 1) * 2]);
        }
        __syncthreads();
        if (tid == 0 && t + 2 < KT) {
            uint32_t b8 = mb + (t & 1) * 8;
            uint32_t sb = sbase + (t & 1) * 40960;
            MBARRIER_EXPECT_TX(b8, 40960);
            bulkcp(sb, Ab + (long)(t + 2) * 20480, b8);
            bulkcp(sb + 20480, Bb + (long)(t + 2) * 20480, b8);
        }
    }

    int q = lane >> 2, tq = lane & 3;

    if (epi == 3) {
        // fused scale/bias/residual + NCHW transpose-out via smem
        float* tile = (float*)dsm;   // [128][129]
#pragma unroll
        for (int nt = 0; nt < 4; nt++) {
            int nl = wn + nt * 8 + tq * 2;
            int n = bn + nl;
            float2 s2 = *(const float2*)(sc + n);
            float2 b2 = *(const float2*)(bi + n);
#pragma unroll
            for (int mt = 0; mt < 4; mt++) {
#pragma unroll
                for (int half = 0; half < 2; half++) {
                    int row = wm + mt * 16 + q + half * 8;
                    long m = bm + row;
                    float2 r2 = *(const float2*)(resid + m * N + n);
                    tile[row * 129 + nl]     = acc[mt][nt][half * 2 + 0] * s2.x + b2.x + r2.x;
                    tile[row * 129 + nl + 1] = acc[mt][nt][half * 2 + 1] * s2.y + b2.y + r2.y;
                }
            }
        }
        __syncthreads();
#pragma unroll
        for (int ci = 0; ci < 16; ci++) {
            int c = wid * 16 + ci;
#pragma unroll
            for (int rc = 0; rc < 4; rc++) {
                int row = rc * 32 + lane;
                long tk = bm + row;
                int b = (int)(tk / 784), tr = (int)(tk % 784);
                Cf[((long)(b * 256 + bn + c)) * 784 + tr] = tile[row * 129 + c];
            }
        }
        return;
    }

#pragma unroll
    for (int nt = 0; nt < 4; nt++) {
        int n = bn + wn + nt * 8 + tq * 2;
        float2 s2 = *(const float2*)(sc + n);
        float2 b2 = *(const float2*)(bi + n);
#pragma unroll
        for (int mt = 0; mt < 4; mt++) {
#pragma unroll
            for (int half = 0; half < 2; half++) {
                long m = bm + wm + mt * 16 + q + half * 8;
                float v0 = acc[mt][nt][half * 2 + 0] * s2.x + b2.x;
                float v1 = acc[mt][nt][half * 2 + 1] * s2.y + b2.y;
                if (epi == 1) {
                    v0 = fmaxf(v0, 0.f);
                    v1 = fmaxf(v1, 0.f);
                } else if (epi == 2) {
                    float2 r2 = *(const float2*)(resid + m * N + n);
                    v0 += r2.x;
                    v1 += r2.y;
                }
                if (Cf) {
                    float2 o;
                    o.x = v0; o.y = v1;
                    *(float2*)(Cf + m * N + n) = o;
                }
                if (Chl) {
                    __nv_bfloat16 h0, l0, h1, l1;
                    split_bf16(v0, h0, l0);
                    split_bf16(v1, h1, l1);
                    __nv_bfloat162 hv, lv;
                    hv.x = h0; hv.y = h1;
                    lv.x = l0; lv.y = l1;
                    long off = img_off(m, n, N);
                    *(__nv_bfloat162*)(Chl + off) = hv;
                    *(__nv_bfloat162*)(Chl + off + 10240) = lv;
                }
            }
        }
    }
}

// ---------------------------------------------------------------------------
// dw0: NCHW input -> NHWC, xA = x + bn(dw3x3(x)); fp32 + blocked hi/lo image
// ---------------------------------------------------------------------------
__global__ void __launch_bounds__(256) dw0_kernel(
    const float* __restrict__ x, const float* __restrict__ w,
    const float* __restrict__ s, const float* __restrict__ bb)
{
    __shared__ float sx[3][64][29];
    __shared__ float wsm[64][9];
    __shared__ float ssm[64], bsm[64];
    int c0 = blockIdx.x * 64;
    int h = blockIdx.y;
    int b = blockIdx.z;
    int tid = threadIdx.x;

    for (int i = tid; i < 64 * 9; i += 256) {
        int c = i / 9, k = i % 9;
        wsm[c][k] = w[(c0 + c) * 9 + k];
    }
    if (tid < 64) { ssm[tid] = s[c0 + tid]; bsm[tid] = bb[c0 + tid]; }

    for (int i = tid; i < 3 * 64 * 28; i += 256) {
        int row = i / 1792;
        int rem = i % 1792;
        int c = rem / 28, ww = rem % 28;
        int hh = h - 1 + row;
        float v = 0.f;
        if (hh >= 0 && hh < 28)
            v = x[(((long)(b * 256 + c0 + c)) * 28 + hh) * 28 + ww];
        sx[row][c][ww] = v;
    }
    __syncthreads();

    for (int i = tid; i < 64 * 28; i += 256) {
        int cl = i & 63, ww = i >> 6;
        float acc = 0.f;
#pragma unroll
        for (int dy = 0; dy < 3; dy++)
#pragma unroll
            for (int dx = 0; dx < 3; dx++) {
                int w2 = ww + dx - 1;
                if (w2 >= 0 && w2 < 28)
                    acc += wsm[cl][dy * 3 + dx] * sx[dy][cl][w2];
            }
        long t = (long)(b * 28 + h) * 28 + ww;
        float v = sx[1][cl][ww] + ssm[cl] * acc + bsm[cl];
        g_xA[t * 256 + c0 + cl] = v;
        __nv_bfloat16 hh2, ll2;
        split_bf16(v, hh2, ll2);
        long off = img_off(t, c0 + cl, 256);
        *(__nv_bfloat16*)(g_xAs + off) = hh2;
        *(__nv_bfloat16*)(g_xAs + off + 10240) = ll2;
    }
}

// ---------------------------------------------------------------------------
// dw1: xB = xA + bn(dw3x3(xA)); fp32 + blocked hi/lo image
// ---------------------------------------------------------------------------
__global__ void __launch_bounds__(256) dw1_kernel(
    const float* __restrict__ w, const float* __restrict__ s,
    const float* __restrict__ bb)
{
    int t = blockIdx.x;
    int c = threadIdx.x;
    int b = t / 784, rem = t % 784, h = rem / 28, ww = rem % 28;
    float wr[9];
#pragma unroll
    for (int k = 0; k < 9; k++) wr[k] = w[c * 9 + k];
    float acc = 0.f;
#pragma unroll
    for (int dy = 0; dy < 3; dy++) {
        int h2 = h + dy - 1;
        if (h2 < 0 || h2 >= 28) continue;
#pragma unroll
        for (int dx = 0; dx < 3; dx++) {
            int w2 = ww + dx - 1;
            if (w2 < 0 || w2 >= 28) continue;
            acc += wr[dy * 3 + dx] * g_xA[((long)(b * 784 + h2 * 28 + w2)) * 256 + c];
        }
    }
    float v = g_xA[(long)t * 256 + c] + s[c] * acc + bb[c];
    g_xB[(long)t * 256 + c] = v;
    __nv_bfloat16 hh, ll;
    split_bf16(v, hh, ll);
    long off = img_off(t, c, 256);
    *(__nv_bfloat16*)(g_xBs + off) = hh;
    *(__nv_bfloat16*)(g_xBs + off + 10240) = ll;
}

// ---------------------------------------------------------------------------
// dws: 5x5 depthwise conv on q channels of g_qkv -> g_q2
// ---------------------------------------------------------------------------
__global__ void __launch_bounds__(256) dws_kernel(
    const float* __restrict__ w, const float* __restrict__ s,
    const float* __restrict__ bb)
{
    int t = blockIdx.x * 4 + (threadIdx.x >> 6);
    int ch = threadIdx.x & 63;
    int head = ch >> 4, kc = ch & 15;
    int qc = head * 96 + kc;
    int b = t / 784, rem = t % 784, h = rem / 28, ww = rem % 28;
    float acc = 0.f;
#pragma unroll
    for (int dy = 0; dy < 5; dy++) {
        int h2 = h + dy - 2;
        if (h2 < 0 || h2 >= 28) continue;
#pragma unroll
        for (int dx = 0; dx < 5; dx++) {
            int w2 = ww + dx - 2;
            if (w2 < 0 || w2 >= 28) continue;
            acc += w[ch * 25 + dy * 5 + dx] *
                   g_qkv[((long)(b * 784 + h2 * 28 + w2)) * 384 + qc];
        }
    }
    g_q2[(long)t * 64 + ch] = s[ch] * acc + bb[ch];
}

// ---------------------------------------------------------------------------
// per-window attention (7x7 = 49 tokens); writes relu(o) blocked hi/lo image
// ---------------------------------------------------------------------------
__global__ void __launch_bounds__(128) attn_kernel(const float* __restrict__ pos)
{
    int wi = blockIdx.x >> 2, wj = blockIdx.x & 3;
    int head = blockIdx.y, b = blockIdx.z;
    int tid = threadIdx.x;

    __shared__ float sq[49 * 17];
    __shared__ float sk[49 * 17];
    __shared__ __align__(16) float sv[49 * 64];
    __shared__ float ss[49 * 50];
    __shared__ int stok[49];

    if (tid < 49) {
        int r = tid;
        stok[r] = b * 784 + (wi * 7 + r / 7) * 28 + wj * 7 + (r % 7);
    }
    __syncthreads();

    for (int i = tid; i < 49 * 16; i += 128) {
        int r = i >> 4, c = i & 15;
        long t = stok[r];
        sq[r * 17 + c] = g_q2[t * 64 + head * 16 + c];
        sk[r * 17 + c] = g_qkv[t * 384 + head * 96 + 16 + c];
    }
    for (int i = tid; i < 49 * 64; i += 128) {
        int r = i >> 6, c = i & 63;
        sv[i] = g_qkv[(long)stok[r] * 384 + head * 96 + 32 + c];
    }
    __syncthreads();

    const float* pe = pos + head * 49 * 49;
    for (int i = tid; i < 49 * 49; i += 128) {
        int qr = i / 49, kr = i % 49;
        float d = 0.f;
#pragma unroll
        for (int c = 0; c < 16; c++)
            d += sq[qr * 17 + c] * sk[kr * 17 + c];
        ss[qr * 50 + kr] = d * 0.25f + pe[i];
    }
    __syncthreads();

    {   // softmax, 2 threads per row + shfl combine
        int r = tid >> 1, hf = tid & 1;
        bool act = r < 49;
        float* row = ss + (act ? r : 0) * 50;
        int k0 = hf ? 25 : 0, cnt = hf ? 24 : 25;
        float mx = -1e30f;
        for (int k = 0; k < cnt; k++) mx = fmaxf(mx, row[k0 + k]);
        mx = fmaxf(mx, __shfl_xor_sync(0xffffffffu, mx, 1));
        float ev[25];
        float sum = 0.f;
        for (int k = 0; k < cnt; k++) {
            ev[k] = __expf(row[k0 + k] - mx);
            sum += ev[k];
        }
        sum += __shfl_xor_sync(0xffffffffu, sum, 1);
        float inv = 1.f / sum;
        if (act)
            for (int k = 0; k < cnt; k++) row[k0 + k] = ev[k] * inv;
    }
    __syncthreads();

    for (int i = tid; i < 49 * 16; i += 128) {
        int qr = i >> 4, d0 = (i & 15) << 2;
        float4 acc = make_float4(0.f, 0.f, 0.f, 0.f);
        for (int k = 0; k < 49; k++) {
            float p = ss[qr * 50 + k];
            float4 v = *(const float4*)&sv[k * 64 + d0];
            acc.x = fmaf(p, v.x, acc.x);
            acc.y = fmaf(p, v.y, acc.y);
            acc.z = fmaf(p, v.z, acc.z);
            acc.w = fmaf(p, v.w, acc.w);
        }
        float r0 = fmaxf(acc.x, 0.f), r1 = fmaxf(acc.y, 0.f);
        float r2 = fmaxf(acc.z, 0.f), r3 = fmaxf(acc.w, 0.f);
        __nv_bfloat16 h0, l0, h1, l1, h2, l2, h3, l3;
        split_bf16(r0, h0, l0);
        split_bf16(r1, h1, l1);
        split_bf16(r2, h2, l2);
        split_bf16(r3, h3, l3);
        long t = stok[qr];
        long off = img_off(t, head * 64 + d0, 256);
        __nv_bfloat162 p01, p23;
        p01.x = h0; p01.y = h1; p23.x = h2; p23.y = h3;
        *(__nv_bfloat162*)(g_obs + off) = p01;
        *(__nv_bfloat162*)(g_obs + off + 4) = p23;
        p01.x = l0; p01.y = l1; p23.x = l2; p23.y = l3;
        *(__nv_bfloat162*)(g_obs + off + 10240) = p01;
        *(__nv_bfloat162*)(g_obs + off + 10244) = p23;
    }
}

// ---------------------------------------------------------------------------
extern "C" void kernel_launch(void* const* d_in, const int* in_sizes, int n_in,
                              void* d_out, int out_size)
{
    const float* in[32];
    for (int i = 0; i < n_in && i < 32; i++) in[i] = (const float*)d_in[i];

    int idw0, idw1, iffn0, iffn1, iqkv, idws, iproj, ipos;
    if (in_sizes[4] > 100000) { // reference-signature order
        idw0 = 1;  iffn0 = 4;  iqkv = 10; idws = 13; iproj = 16;
        ipos = 19; idw1 = 20;  iffn1 = 23;
    } else {                    // setup_inputs dict order
        idw0 = 1;  idw1 = 4;   iffn0 = 7;  iffn1 = 13;
        iqkv = 19; idws = 22;  iproj = 25; ipos = 28;
    }

    const float* x     = in[0];
    const float* dw0_w = in[idw0],  * dw0_s = in[idw0 + 1], * dw0_b = in[idw0 + 2];
    const float* dw1_w = in[idw1],  * dw1_s = in[idw1 + 1], * dw1_b = in[idw1 + 2];
    const float* f0w1 = in[iffn0],     * f0s1 = in[iffn0 + 1], * f0b1 = in[iffn0 + 2];
    const float* f0w2 = in[iffn0 + 3], * f0s2 = in[iffn0 + 4], * f0b2 = in[iffn0 + 5];
    const float* f1w1 = in[iffn1],     * f1s1 = in[iffn1 + 1], * f1b1 = in[iffn1 + 2];
    const float* f1w2 = in[iffn1 + 3], * f1s2 = in[iffn1 + 4], * f1b2 = in[iffn1 + 5];
    const float* qkv_w = in[iqkv],  * qkv_s = in[iqkv + 1],  * qkv_b = in[iqkv + 2];
    const float* dws_w = in[idws],  * dws_s = in[idws + 1],  * dws_b = in[idws + 2];
    const float* proj_w = in[iproj], * proj_s = in[iproj + 1], * proj_b = in[iproj + 2];
    const float* pos = in[ipos];

    float *pxA, *pxB, *pqkv;
    unsigned char *pxAs, *phs, *pobs, *pxBs, *pwtB;
    cudaGetSymbolAddress((void**)&pxA, g_xA);
    cudaGetSymbolAddress((void**)&pxB, g_xB);
    cudaGetSymbolAddress((void**)&pqkv, g_qkv);
    cudaGetSymbolAddress((void**)&pxAs, g_xAs);
    cudaGetSymbolAddress((void**)&phs,  g_hs);
    cudaGetSymbolAddress((void**)&pobs, g_obs);
    cudaGetSymbolAddress((void**)&pxBs, g_xBs);
    cudaGetSymbolAddress((void**)&pwtB, g_wtB);

    const int SMEM_GEMM = 81920;
    cudaFuncSetAttribute(mm_gemm, cudaFuncAttributeMaxDynamicSharedMemorySize,
                         SMEM_GEMM);

    // split all weights into blocked bf16 hi/lo images (one launch)
    wconv_all<<<(688128 + 255) / 256, 256>>>(f0w1, f0w2, qkv_w, proj_w, f1w1,
                                             f1w2, pwtB);

    // 1. xA = x + bn(dw3x3(x))    (NCHW -> NHWC, + image)
    dw0_kernel<<<dim3(4, 28, 64), 256>>>(x, dw0_w, dw0_s, dw0_b);

    // 2. ffn0
    mm_gemm<<<dim3(4, 392), 256, SMEM_GEMM>>>(
        pxAs, pwtB + WB_F0W1, f0s1, f0b1, nullptr, nullptr, phs, 512, 256, 1);
    mm_gemm<<<dim3(2, 392), 256, SMEM_GEMM>>>(
        phs, pwtB + WB_F0W2, f0s2, f0b2, pxA, pxA, pxAs, 256, 512, 2);

    // 3. attention
    mm_gemm<<<dim3(3, 392), 256, SMEM_GEMM>>>(
        pxAs, pwtB + WB_QKV, qkv_s, qkv_b, nullptr, pqkv, nullptr, 384, 256, 0);
    dws_kernel<<<TOK / 4, 256>>>(dws_w, dws_s, dws_b);
    attn_kernel<<<dim3(16, 4, 64), 128>>>(pos);
    mm_gemm<<<dim3(2, 392), 256, SMEM_GEMM>>>(
        pobs, pwtB + WB_PROJ, proj_s, proj_b, pxA, pxA, nullptr, 256, 256, 2);

    // 4. xB = xA + bn(dw3x3(xA))
    dw1_kernel<<<TOK, 256>>>(dw1_w, dw1_s, dw1_b);

    // 5. ffn1: h then FINAL gemm writes d_out in NCHW directly (epi=3)
    mm_gemm<<<dim3(4, 392), 256, SMEM_GEMM>>>(
        pxBs, pwtB + WB_F1W1, f1s1, f1b1, nullptr, nullptr, phs, 512, 256, 1);
    mm_gemm<<<dim3(2, 392), 256, SMEM_GEMM>>>(
        phs, pwtB + WB_F1W2, f1s2, f1b2, pxB, (float*)d_out, nullptr,
        256, 512, 3);
}

// round 13
// speedup vs baseline: 2.3649x; 1.0246x over previous
#include <cuda_runtime.h>
#include <cuda_bf16.h>
#include <cstdint>

// ---------------------------------------------------------------------------
// EfficientViT block. HMMA mma.sync bf16 hi/lo-split GEMMs, blocked bf16
// images as the ONLY activation storage (residuals reconstruct hi+lo),
// cp.async.bulk mainloop, smem-tiled dws, f32x2-packed attention math.
// ---------------------------------------------------------------------------

#define TOK   50176

__device__ float g_qkv[TOK * 384];
__device__ float g_q2[TOK * 64];

// blocked hi/lo bf16 images: [128 rows x 32 k] tiles, stride 40, hi+lo = 20480B
__device__ __align__(16) unsigned char g_xAs[TOK * 256 * 5];
__device__ __align__(16) unsigned char g_hs [TOK * 512 * 5];
__device__ __align__(16) unsigned char g_obs[TOK * 256 * 5];
__device__ __align__(16) unsigned char g_xBs[TOK * 256 * 5];
__device__ __align__(16) unsigned char g_wtB[3440640];

#define WB_F0W1 0
#define WB_F0W2 655360
#define WB_QKV  1310720
#define WB_PROJ 1802240
#define WB_F1W1 2129920
#define WB_F1W2 2785280

__device__ __forceinline__ uint32_t smem_u32(const void* p) {
    uint32_t a;
    asm("{ .reg .u64 t; cvta.to.shared.u64 t, %1; cvt.u32.u64 %0, t; }"
        : "=r"(a) : "l"(p));
    return a;
}
__device__ __forceinline__ void ldsm4(uint32_t* r, uint32_t addr) {
    asm volatile("ldmatrix.sync.aligned.m8n8.x4.shared.b16 {%0,%1,%2,%3}, [%4];"
        : "=r"(r[0]), "=r"(r[1]), "=r"(r[2]), "=r"(r[3]) : "r"(addr));
}
__device__ __forceinline__ void mma16816(float* c, const uint32_t* a,
                                         const uint32_t* b) {
    asm volatile(
        "mma.sync.aligned.m16n8k16.row.col.f32.bf16.bf16.f32 "
        "{%0,%1,%2,%3}, {%4,%5,%6,%7}, {%8,%9}, {%0,%1,%2,%3};"
        : "+f"(c[0]), "+f"(c[1]), "+f"(c[2]), "+f"(c[3])
        : "r"(a[0]), "r"(a[1]), "r"(a[2]), "r"(a[3]), "r"(b[0]), "r"(b[1]));
}

// packed f32x2 FMA (Blackwell FFMA2)
__device__ __forceinline__ unsigned long long pack2f(float lo, float hi) {
    unsigned long long r;
    asm("mov.b64 %0, {%1,%2};" : "=l"(r) : "f"(lo), "f"(hi));
    return r;
}
__device__ __forceinline__ void ffma2(unsigned long long& d,
                                      unsigned long long a,
                                      unsigned long long b) {
    asm("fma.rn.f32x2 %0, %1, %2, %3;" : "=l"(d) : "l"(a), "l"(b), "l"(d));
}
__device__ __forceinline__ float2 unpack2f(unsigned long long v) {
    float2 f;
    asm("mov.b64 {%0,%1}, %2;" : "=f"(f.x), "=f"(f.y) : "l"(v));
    return f;
}

#define MBARRIER_INIT(mbar_addr, count) \
    asm volatile("mbarrier.init.shared.b64 [%0], %1;" \
        :: "r"((uint32_t)(mbar_addr)), "r"((uint32_t)(count)) : "memory")
#define MBARRIER_EXPECT_TX(mbar_addr, tx_bytes) \
    asm volatile("mbarrier.arrive.expect_tx.shared.b64 _, [%0], %1;" \
        :: "r"((uint32_t)(mbar_addr)), "r"((uint32_t)(tx_bytes)) : "memory")
#define MBARRIER_WAIT_PARITY(mbar_addr, parity) do { \
    uint32_t _mbar = (uint32_t)(mbar_addr); \
    uint32_t _par = (uint32_t)(parity); \
    uint32_t _done; \
    asm volatile( \
        "{\n\t.reg .pred p;\n\t" \
        "mbarrier.try_wait.parity.acquire.cta.shared::cta.b64 p, [%1], %2;\n\t" \
        "selp.b32 %0, 1, 0, p;\n\t}" \
        : "=r"(_done) : "r"(_mbar), "r"(_par) : "memory"); \
    if (!_done) { \
        asm volatile( \
            "{\n\t.reg .pred P1;\n\t" \
            "WAIT_LOOP_%=:\n\t" \
            "mbarrier.try_wait.parity.acquire.cta.shared::cta.b64 P1, [%0], %1, 0x989680;\n\t" \
            "@P1 bra.uni WAIT_DONE_%=;\n\t" \
            "bra.uni WAIT_LOOP_%=;\n\t" \
            "WAIT_DONE_%=:\n\t}" \
            :: "r"(_mbar), "r"(_par) : "memory"); \
    } \
} while (0)

__device__ __forceinline__ void bulkcp(uint32_t dst, const void* src,
                                       uint32_t mbar) {
    asm volatile(
        "cp.async.bulk.shared::cta.global.mbarrier::complete_tx::bytes "
        "[%0], [%1], %2, [%3];"
        :: "r"(dst), "l"(src), "r"(20480u), "r"(mbar) : "memory");
}

// blocked-image byte offset of (row, col) hi element; lo at +10240
__device__ __forceinline__ long img_off(long row, int col, int Kd) {
    return ((row >> 7) * (Kd >> 5) + (col >> 5)) * 20480L +
           (row & 127) * 80 + (col & 31) * 2;
}
__device__ __forceinline__ float img_read(const unsigned char* img, long row,
                                          int col, int Kd) {
    long off = img_off(row, col, Kd);
    return __bfloat162float(*(const __nv_bfloat16*)(img + off)) +
           __bfloat162float(*(const __nv_bfloat16*)(img + off + 10240));
}

#define TS 40
__device__ __forceinline__ uint32_t a_addr(uint32_t base, int m, int k, int lane) {
    int g = lane >> 3, r = lane & 7;
    return base + ((m + ((g & 1) << 3) + r) * TS + k + ((g >> 1) << 3)) * 2;
}
__device__ __forceinline__ uint32_t b_addr(uint32_t base, int n, int k, int lane) {
    int g = lane >> 3, r = lane & 7;
    return base + ((n + ((g >> 1) << 3) + r) * TS + k + ((g & 1) << 3)) * 2;
}

__device__ __forceinline__ void split_bf16(float v, __nv_bfloat16& h,
                                           __nv_bfloat16& l) {
    h = __float2bfloat16(v);
    l = __float2bfloat16(v - __bfloat162float(h));
}
__device__ __forceinline__ void img_write(unsigned char* img, long row, int col,
                                          int Kd, float v0, float v1) {
    __nv_bfloat16 h0, l0, h1, l1;
    split_bf16(v0, h0, l0);
    split_bf16(v1, h1, l1);
    long off = img_off(row, col, Kd);
    __nv_bfloat162 hv, lv;
    hv.x = h0; hv.y = h1;
    lv.x = l0; lv.y = l1;
    *(__nv_bfloat162*)(img + off) = hv;
    *(__nv_bfloat162*)(img + off + 10240) = lv;
}

// ---------------------------------------------------------------------------
// All-weights split into blocked images, one launch
// ---------------------------------------------------------------------------
__global__ void wconv_all(const float* __restrict__ w0, const float* __restrict__ w1,
                          const float* __restrict__ w2, const float* __restrict__ w3,
                          const float* __restrict__ w4, const float* __restrict__ w5,
                          unsigned char* __restrict__ dst) {
    long i = (long)blockIdx.x * 256 + threadIdx.x;
    if (i >= 688128) return;
    const long cum[7] = {0, 131072, 262144, 360448, 425984, 557056, 688128};
    const long ob[6] = {WB_F0W1, WB_F0W2, WB_QKV, WB_PROJ, WB_F1W1, WB_F1W2};
    const int Ks[6] = {256, 512, 256, 256, 256, 512};
    const float* srcs[6] = {w0, w1, w2, w3, w4, w5};
    int s = 0;
    while (i >= cum[s + 1]) s++;
    long j = i - cum[s];
    int K = Ks[s];
    long n = j / K;
    int k = (int)(j % K);
    __nv_bfloat16 h, l;
    split_bf16(srcs[s][j], h, l);
    long off = ob[s] + img_off(n, k, K);
    *(__nv_bfloat16*)(dst + off) = h;
    *(__nv_bfloat16*)(dst + off + 10240) = l;
}

// ---------------------------------------------------------------------------
// HMMA GEMM. epi: 0 fp32 out ; 1 relu->img ; 2 resid(img)+ ->img (in-place ok)
//             3 resid(img)+ -> NCHW fp32 transpose out
// ---------------------------------------------------------------------------
__global__ void __launch_bounds__(256, 2) mm_gemm(
    const unsigned char* __restrict__ Aimg, const unsigned char* __restrict__ Bimg,
    const float* __restrict__ sc, const float* __restrict__ bi,
    const unsigned char* __restrict__ residImg, float* __restrict__ Cf,
    unsigned char* __restrict__ Chl,
    int N, int K, int epi)
{
    extern __shared__ __align__(128) unsigned char dsm[];
    __shared__ __align__(8) unsigned long long mbars[2];
    int tid = threadIdx.x, lane = tid & 31, wid = tid >> 5;
    int wm = (wid & 1) << 6, wn = (wid >> 1) << 5;
    long bm = (long)blockIdx.y << 7;
    int bn = blockIdx.x << 7;
    int KT = K >> 5;

    float acc[4][4][4] = {};
    uint32_t sbase = smem_u32(dsm);
    uint32_t mb = smem_u32(mbars);

    if (tid == 0) {
        MBARRIER_INIT(mb, 1);
        MBARRIER_INIT(mb + 8, 1);
    }
    __syncthreads();

    const unsigned char* Ab = Aimg + (long)blockIdx.y * KT * 20480;
    const unsigned char* Bb = Bimg + (long)blockIdx.x * KT * 20480;

    if (tid == 0) {
        MBARRIER_EXPECT_TX(mb, 40960);
        bulkcp(sbase, Ab, mb);
        bulkcp(sbase + 20480, Bb, mb);
        if (KT > 1) {
            MBARRIER_EXPECT_TX(mb + 8, 40960);
            bulkcp(sbase + 40960, Ab + 20480, mb + 8);
            bulkcp(sbase + 61440, Bb + 20480, mb + 8);
        }
    }

    for (int t = 0; t < KT; t++) {
        MBARRIER_WAIT_PARITY(mb + (t & 1) * 8, (t >> 1) & 1);
        uint32_t sAh = sbase + (t & 1) * 40960;
        uint32_t sAl = sAh + 10240;
        uint32_t sBh = sAh + 20480;
        uint32_t sBl = sAh + 30720;
#pragma unroll
        for (int kk = 0; kk < 32; kk += 16) {
            uint32_t ah[4][4], al[4][4], bh[2][4], bl[2][4];
#pragma unroll
            for (int mt = 0; mt < 4; mt++)
                ldsm4(ah[mt], a_addr(sAh, wm + mt * 16, kk, lane));
#pragma unroll
            for (int h = 0; h < 2; h++)
                ldsm4(bh[h], b_addr(sBh, wn + h * 16, kk, lane));
#pragma unroll
            for (int mt = 0; mt < 4; mt++)
#pragma unroll
                for (int nt = 0; nt < 4; nt++)
                    mma16816(acc[mt][nt], ah[mt], &bh[nt >> 1][(nt & 1) * 2]);
#pragma unroll
            for (int h = 0; h < 2; h++)
                ldsm4(bl[h], b_addr(sBl, wn + h * 16, kk, lane));
#pragma unroll
            for (int mt = 0; mt < 4; mt++)
#pragma unroll
                for (int nt = 0; nt < 4; nt++)
                    mma16816(acc[mt][nt], ah[mt], &bl[nt >> 1][(nt & 1) * 2]);
#pragma unroll
            for (int mt = 0; mt < 4; mt++)
                ldsm4(al[mt], a_addr(sAl, wm + mt * 16, kk, lane));
#pragma unroll
            for (int mt = 0; mt < 4; mt++)
#pragma unroll
                for (int nt = 0; nt < 4; nt++)
                    mma16816(acc[mt][nt], al[mt], &bh[nt >> 1][(nt & 1) * 2]);
        }
        __syncthreads();
        if (tid == 0 && t + 2 < KT) {
            uint32_t b8 = mb + (t & 1) * 8;
            uint32_t sb = sbase + (t & 1) * 40960;
            MBARRIER_EXPECT_TX(b8, 40960);
            bulkcp(sb, Ab + (long)(t + 2) * 20480, b8);
            bulkcp(sb + 20480, Bb + (long)(t + 2) * 20480, b8);
        }
    }

    int q = lane >> 2, tq = lane & 3;

    if (epi == 3) {
        float* tile = (float*)dsm;   // [128][129]
#pragma unroll
        for (int nt = 0; nt < 4; nt++) {
            int nl = wn + nt * 8 + tq * 2;
            int n = bn + nl;
            float2 s2 = *(const float2*)(sc + n);
            float2 b2 = *(const float2*)(bi + n);
#pragma unroll
            for (int mt = 0; mt < 4; mt++) {
#pragma unroll
                for (int half = 0; half < 2; half++) {
                    int row = wm + mt * 16 + q + half * 8;
                    long m = bm + row;
                    long off = img_off(m, n, N);
                    __nv_bfloat162 rh = *(const __nv_bfloat162*)(residImg + off);
                    __nv_bfloat162 rl = *(const __nv_bfloat162*)(residImg + off + 10240);
                    tile[row * 129 + nl]     = acc[mt][nt][half * 2 + 0] * s2.x + b2.x +
                        __bfloat162float(rh.x) + __bfloat162float(rl.x);
                    tile[row * 129 + nl + 1] = acc[mt][nt][half * 2 + 1] * s2.y + b2.y +
                        __bfloat162float(rh.y) + __bfloat162float(rl.y);
                }
            }
        }
        __syncthreads();
#pragma unroll
        for (int ci = 0; ci < 16; ci++) {
            int c = wid * 16 + ci;
#pragma unroll
            for (int rc = 0; rc < 4; rc++) {
                int row = rc * 32 + lane;
                long tk = bm + row;
                int b = (int)(tk / 784), tr = (int)(tk % 784);
                Cf[((long)(b * 256 + bn + c)) * 784 + tr] = tile[row * 129 + c];
            }
        }
        return;
    }

#pragma unroll
    for (int nt = 0; nt < 4; nt++) {
        int n = bn + wn + nt * 8 + tq * 2;
        float2 s2 = *(const float2*)(sc + n);
        float2 b2 = *(const float2*)(bi + n);
#pragma unroll
        for (int mt = 0; mt < 4; mt++) {
#pragma unroll
            for (int half = 0; half < 2; half++) {
                long m = bm + wm + mt * 16 + q + half * 8;
                float v0 = acc[mt][nt][half * 2 + 0] * s2.x + b2.x;
                float v1 = acc[mt][nt][half * 2 + 1] * s2.y + b2.y;
                if (epi == 1) {
                    v0 = fmaxf(v0, 0.f);
                    v1 = fmaxf(v1, 0.f);
                } else if (epi == 2) {
                    long off = img_off(m, n, N);
                    __nv_bfloat162 rh = *(const __nv_bfloat162*)(residImg + off);
                    __nv_bfloat162 rl = *(const __nv_bfloat162*)(residImg + off + 10240);
                    v0 += __bfloat162float(rh.x) + __bfloat162float(rl.x);
                    v1 += __bfloat162float(rh.y) + __bfloat162float(rl.y);
                }
                if (epi == 0) {
                    float2 o;
                    o.x = v0; o.y = v1;
                    *(float2*)(Cf + m * N + n) = o;
                } else {
                    img_write(Chl, m, n, N, v0, v1);
                }
            }
        }
    }
}

// ---------------------------------------------------------------------------
// dw0: NCHW input -> blocked image only, xA = x + bn(dw3x3(x))
// ---------------------------------------------------------------------------
__global__ void __launch_bounds__(256) dw0_kernel(
    const float* __restrict__ x, const float* __restrict__ w,
    const float* __restrict__ s, const float* __restrict__ bb)
{
    __shared__ float sx[3][64][29];
    __shared__ float wsm[64][9];
    __shared__ float ssm[64], bsm[64];
    int c0 = blockIdx.x * 64;
    int h = blockIdx.y;
    int b = blockIdx.z;
    int tid = threadIdx.x;

    for (int i = tid; i < 64 * 9; i += 256) {
        int c = i / 9, k = i % 9;
        wsm[c][k] = w[(c0 + c) * 9 + k];
    }
    if (tid < 64) { ssm[tid] = s[c0 + tid]; bsm[tid] = bb[c0 + tid]; }

    for (int i = tid; i < 3 * 64 * 28; i += 256) {
        int row = i / 1792;
        int rem = i % 1792;
        int c = rem / 28, ww = rem % 28;
        int hh = h - 1 + row;
        float v = 0.f;
        if (hh >= 0 && hh < 28)
            v = x[(((long)(b * 256 + c0 + c)) * 28 + hh) * 28 + ww];
        sx[row][c][ww] = v;
    }
    __syncthreads();

    for (int i = tid; i < 64 * 28; i += 256) {
        int cl = i & 63, ww = i >> 6;
        float acc = 0.f;
#pragma unroll
        for (int dy = 0; dy < 3; dy++)
#pragma unroll
            for (int dx = 0; dx < 3; dx++) {
                int w2 = ww + dx - 1;
                if (w2 >= 0 && w2 < 28)
                    acc += wsm[cl][dy * 3 + dx] * sx[dy][cl][w2];
            }
        long t = (long)(b * 28 + h) * 28 + ww;
        float v = sx[1][cl][ww] + ssm[cl] * acc + bsm[cl];
        __nv_bfloat16 hh2, ll2;
        split_bf16(v, hh2, ll2);
        long off = img_off(t, c0 + cl, 256);
        *(__nv_bfloat16*)(g_xAs + off) = hh2;
        *(__nv_bfloat16*)(g_xAs + off + 10240) = ll2;
    }
}

// ---------------------------------------------------------------------------
// dw1: xB = xA + bn(dw3x3(xA)) from/to blocked images
// ---------------------------------------------------------------------------
__global__ void __launch_bounds__(256) dw1_kernel(
    const float* __restrict__ w, const float* __restrict__ s,
    const float* __restrict__ bb)
{
    int t = blockIdx.x;
    int c = threadIdx.x;
    int b = t / 784, rem = t % 784, h = rem / 28, ww = rem % 28;
    float wr[9];
#pragma unroll
    for (int k = 0; k < 9; k++) wr[k] = w[c * 9 + k];
    float acc = 0.f, center = 0.f;
#pragma unroll
    for (int dy = 0; dy < 3; dy++) {
        int h2 = h + dy - 1;
        if (h2 < 0 || h2 >= 28) continue;
#pragma unroll
        for (int dx = 0; dx < 3; dx++) {
            int w2 = ww + dx - 1;
            if (w2 < 0 || w2 >= 28) continue;
            float v = img_read(g_xAs, (long)(b * 784 + h2 * 28 + w2), c, 256);
            acc += wr[dy * 3 + dx] * v;
            if (dy == 1 && dx == 1) center = v;
        }
    }
    float out = center + s[c] * acc + bb[c];
    __nv_bfloat16 hh, ll;
    split_bf16(out, hh, ll);
    long off = img_off(t, c, 256);
    *(__nv_bfloat16*)(g_xBs + off) = hh;
    *(__nv_bfloat16*)(g_xBs + off + 10240) = ll;
}

// ---------------------------------------------------------------------------
// dws: 5x5 depthwise conv, smem-tiled per (batch, head). grid (64, 4), 256 thr
// ---------------------------------------------------------------------------
__global__ void __launch_bounds__(256) dws_kernel(
    const float* __restrict__ w, const float* __restrict__ s,
    const float* __restrict__ bb)
{
    extern __shared__ float sx[];   // [784][17]
    int b = blockIdx.x, head = blockIdx.y;
    int tid = threadIdx.x;
    int kc = tid & 15, tg = tid >> 4;

    for (int i = tid; i < 784 * 16; i += 256) {
        int t = i >> 4, k2 = i & 15;
        sx[t * 17 + k2] = g_qkv[((long)(b * 784 + t)) * 384 + head * 96 + k2];
    }
    __syncthreads();

    int ch = head * 16 + kc;
    float wr[25];
#pragma unroll
    for (int k = 0; k < 25; k++) wr[k] = w[ch * 25 + k];
    float sv = s[ch], bv = bb[ch];

    for (int j = 0; j < 49; j++) {
        int t = tg + (j << 4);
        int h = t / 28, ww = t % 28;
        float acc = 0.f;
#pragma unroll
        for (int dy = 0; dy < 5; dy++) {
            int h2 = h + dy - 2;
            if (h2 < 0 || h2 >= 28) continue;
#pragma unroll
            for (int dx = 0; dx < 5; dx++) {
                int w2 = ww + dx - 2;
                if (w2 < 0 || w2 >= 28) continue;
                acc += wr[dy * 5 + dx] * sx[(h2 * 28 + w2) * 17 + kc];
            }
        }
        g_q2[((long)(b * 784 + t)) * 64 + ch] = sv * acc + bv;
    }
}

// ---------------------------------------------------------------------------
// per-window attention (7x7 = 49 tokens), f32x2-packed math; out -> obs image
// ---------------------------------------------------------------------------
__global__ void __launch_bounds__(128) attn_kernel(const float* __restrict__ pos)
{
    int wi = blockIdx.x >> 2, wj = blockIdx.x & 3;
    int head = blockIdx.y, b = blockIdx.z;
    int tid = threadIdx.x;

    __shared__ __align__(8) float sq[49 * 18];
    __shared__ __align__(8) float sk[49 * 18];
    __shared__ __align__(16) float sv[49 * 64];
    __shared__ __align__(8) float ss[49 * 50];
    __shared__ int stok[49];

    if (tid < 49) {
        int r = tid;
        stok[r] = b * 784 + (wi * 7 + r / 7) * 28 + wj * 7 + (r % 7);
    }
    __syncthreads();

    for (int i = tid; i < 49 * 16; i += 128) {
        int r = i >> 4, c = i & 15;
        long t = stok[r];
        sq[r * 18 + c] = g_q2[t * 64 + head * 16 + c];
        sk[r * 18 + c] = g_qkv[t * 384 + head * 96 + 16 + c];
    }
    for (int i = tid; i < 49 * 64; i += 128) {
        int r = i >> 6, c = i & 63;
        sv[i] = g_qkv[(long)stok[r] * 384 + head * 96 + 32 + c];
    }
    __syncthreads();

    const float* pe = pos + head * 49 * 49;
    for (int i = tid; i < 49 * 49; i += 128) {
        int qr = i / 49, kr = i % 49;
        unsigned long long d2 = pack2f(0.f, 0.f);
#pragma unroll
        for (int cc = 0; cc < 8; cc++) {
            unsigned long long a2 = *(const unsigned long long*)&sq[qr * 18 + cc * 2];
            unsigned long long b2 = *(const unsigned long long*)&sk[kr * 18 + cc * 2];
            ffma2(d2, a2, b2);
        }
        float2 f = unpack2f(d2);
        ss[qr * 50 + kr] = (f.x + f.y) * 0.25f + pe[i];
    }
    __syncthreads();

    {   // softmax, 2 threads per row + shfl combine
        int r = tid >> 1, hf = tid & 1;
        bool act = r < 49;
        float* row = ss + (act ? r : 0) * 50;
        int k0 = hf ? 25 : 0, cnt = hf ? 24 : 25;
        float mx = -1e30f;
        for (int k = 0; k < cnt; k++) mx = fmaxf(mx, row[k0 + k]);
        mx = fmaxf(mx, __shfl_xor_sync(0xffffffffu, mx, 1));
        float ev[25];
        float sum = 0.f;
        for (int k = 0; k < cnt; k++) {
            ev[k] = __expf(row[k0 + k] - mx);
            sum += ev[k];
        }
        sum += __shfl_xor_sync(0xffffffffu, sum, 1);
        float inv = 1.f / sum;
        if (act)
            for (int k = 0; k < cnt; k++) row[k0 + k] = ev[k] * inv;
    }
    __syncthreads();

    for (int i = tid; i < 49 * 16; i += 128) {
        int qr = i >> 4, d0 = (i & 15) << 2;
        unsigned long long a01 = pack2f(0.f, 0.f), a23 = pack2f(0.f, 0.f);
        for (int k = 0; k < 49; k++) {
            float p = ss[qr * 50 + k];
            unsigned long long p2 = pack2f(p, p);
            ffma2(a01, p2, *(const unsigned long long*)&sv[k * 64 + d0]);
            ffma2(a23, p2, *(const unsigned long long*)&sv[k * 64 + d0 + 2]);
        }
        float2 f01 = unpack2f(a01), f23 = unpack2f(a23);
        float r0 = fmaxf(f01.x, 0.f), r1 = fmaxf(f01.y, 0.f);
        float r2 = fmaxf(f23.x, 0.f), r3 = fmaxf(f23.y, 0.f);
        long t = stok[qr];
        img_write(g_obs, t, head * 64 + d0, 256, r0, r1);
        img_write(g_obs, t, head * 64 + d0 + 2, 256, r2, r3);
    }
}

// ---------------------------------------------------------------------------
extern "C" void kernel_launch(void* const* d_in, const int* in_sizes, int n_in,
                              void* d_out, int out_size)
{
    const float* in[32];
    for (int i = 0; i < n_in && i < 32; i++) in[i] = (const float*)d_in[i];

    int idw0, idw1, iffn0, iffn1, iqkv, idws, iproj, ipos;
    if (in_sizes[4] > 100000) { // reference-signature order
        idw0 = 1;  iffn0 = 4;  iqkv = 10; idws = 13; iproj = 16;
        ipos = 19; idw1 = 20;  iffn1 = 23;
    } else {                    // setup_inputs dict order
        idw0 = 1;  idw1 = 4;   iffn0 = 7;  iffn1 = 13;
        iqkv = 19; idws = 22;  iproj = 25; ipos = 28;
    }

    const float* x     = in[0];
    const float* dw0_w = in[idw0],  * dw0_s = in[idw0 + 1], * dw0_b = in[idw0 + 2];
    const float* dw1_w = in[idw1],  * dw1_s = in[idw1 + 1], * dw1_b = in[idw1 + 2];
    const float* f0w1 = in[iffn0],     * f0s1 = in[iffn0 + 1], * f0b1 = in[iffn0 + 2];
    const float* f0w2 = in[iffn0 + 3], * f0s2 = in[iffn0 + 4], * f0b2 = in[iffn0 + 5];
    const float* f1w1 = in[iffn1],     * f1s1 = in[iffn1 + 1], * f1b1 = in[iffn1 + 2];
    const float* f1w2 = in[iffn1 + 3], * f1s2 = in[iffn1 + 4], * f1b2 = in[iffn1 + 5];
    const float* qkv_w = in[iqkv],  * qkv_s = in[iqkv + 1],  * qkv_b = in[iqkv + 2];
    const float* dws_w = in[idws],  * dws_s = in[idws + 1],  * dws_b = in[idws + 2];
    const float* proj_w = in[iproj], * proj_s = in[iproj + 1], * proj_b = in[iproj + 2];
    const float* pos = in[ipos];

    float* pqkv;
    unsigned char *pxAs, *phs, *pobs, *pxBs, *pwtB;
    cudaGetSymbolAddress((void**)&pqkv, g_qkv);
    cudaGetSymbolAddress((void**)&pxAs, g_xAs);
    cudaGetSymbolAddress((void**)&phs,  g_hs);
    cudaGetSymbolAddress((void**)&pobs, g_obs);
    cudaGetSymbolAddress((void**)&pxBs, g_xBs);
    cudaGetSymbolAddress((void**)&pwtB, g_wtB);

    const int SMEM_GEMM = 81920;
    cudaFuncSetAttribute(mm_gemm, cudaFuncAttributeMaxDynamicSharedMemorySize,
                         SMEM_GEMM);
    const int SMEM_DWS = 784 * 17 * 4;
    cudaFuncSetAttribute(dws_kernel, cudaFuncAttributeMaxDynamicSharedMemorySize,
                         SMEM_DWS);

    wconv_all<<<(688128 + 255) / 256, 256>>>(f0w1, f0w2, qkv_w, proj_w, f1w1,
                                             f1w2, pwtB);

    // 1. xA = x + bn(dw3x3(x))  -> image
    dw0_kernel<<<dim3(4, 28, 64), 256>>>(x, dw0_w, dw0_s, dw0_b);

    // 2. ffn0 (h image; then in-place xA image += ffn)
    mm_gemm<<<dim3(4, 392), 256, SMEM_GEMM>>>(
        pxAs, pwtB + WB_F0W1, f0s1, f0b1, nullptr, nullptr, phs, 512, 256, 1);
    mm_gemm<<<dim3(2, 392), 256, SMEM_GEMM>>>(
        phs, pwtB + WB_F0W2, f0s2, f0b2, pxAs, nullptr, pxAs, 256, 512, 2);

    // 3. attention
    mm_gemm<<<dim3(3, 392), 256, SMEM_GEMM>>>(
        pxAs, pwtB + WB_QKV, qkv_s, qkv_b, nullptr, pqkv, nullptr, 384, 256, 0);
    dws_kernel<<<dim3(64, 4), 256, SMEM_DWS>>>(dws_w, dws_s, dws_b);
    attn_kernel<<<dim3(16, 4, 64), 128>>>(pos);
    mm_gemm<<<dim3(2, 392), 256, SMEM_GEMM>>>(
        pobs, pwtB + WB_PROJ, proj_s, proj_b, pxAs, nullptr, pxAs, 256, 256, 2);

    // 4. xB image = xA + bn(dw3x3(xA))
    dw1_kernel<<<TOK, 256>>>(dw1_w, dw1_s, dw1_b);

    // 5. ffn1: h image, then final GEMM -> NCHW d_out (epi=3, resid xB image)
    mm_gemm<<<dim3(4, 392), 256, SMEM_GEMM>>>(
        pxBs, pwtB + WB_F1W1, f1s1, f1b1, nullptr, nullptr, phs, 512, 256, 1);
    mm_gemm<<<dim3(2, 392), 256, SMEM_GEMM>>>(
        phs, pwtB + WB_F1W2, f1s2, f1b2, pxBs, (float*)d_out, nullptr,
        256, 512, 3);
}